// round 5
// baseline (speedup 1.0000x reference)
#include <cuda_runtime.h>
#include <cuda_bf16.h>
#include <cstdint>

#define B_SZ   2
#define LQ     4096
#define LKV    1024
#define DMODEL 512
#define HEADS  8
#define DHEAD  64
#define SPAN   64
#define STRIDE 4

#define MQ (B_SZ * LQ)    // 8192
#define MK (B_SZ * LKV)   // 2048

// ---------------- scratch ----------------
__device__ __nv_bfloat16 g_qh[MQ * DMODEL], g_ql[MQ * DMODEL];
__device__ __nv_bfloat16 g_kh[MK * DMODEL], g_kl[MK * DMODEL];
__device__ __nv_bfloat16 g_vh[MK * DMODEL], g_vl[MK * DMODEL];
__device__ __nv_bfloat16 g_Qph[MQ * DMODEL], g_Qpl[MQ * DMODEL];
__device__ __nv_bfloat16 g_Kph[MK * DMODEL], g_Kpl[MK * DMODEL];
__device__ __nv_bfloat16 g_Vph[MK * DMODEL], g_Vpl[MK * DMODEL];
__device__ __nv_bfloat16 g_ch[MQ * DMODEL], g_cl[MQ * DMODEL];
__device__ __nv_bfloat16 g_Wth[4 * DMODEL * DMODEL], g_Wtl[4 * DMODEL * DMODEL];

// ---------------- helpers ----------------
__device__ __forceinline__ uint32_t smem_u32(const void* p) {
    uint32_t a;
    asm("{ .reg .u64 t; cvta.to.shared.u64 t, %1; cvt.u32.u64 %0, t; }" : "=r"(a) : "l"(p));
    return a;
}
__device__ __forceinline__ void bf16_split(float x, __nv_bfloat16& h, __nv_bfloat16& l) {
    h = __float2bfloat16_rn(x);
    l = __float2bfloat16_rn(x - __bfloat162float(h));
}
__device__ __forceinline__ uint32_t pack_bf2(float a, float b) {
    __nv_bfloat162 t(__float2bfloat16_rn(a), __float2bfloat16_rn(b));
    return *(uint32_t*)&t;
}
__device__ __forceinline__ void ldsm_x4(uint32_t* r, uint32_t a) {
    asm volatile("ldmatrix.sync.aligned.m8n8.x4.shared.b16 {%0,%1,%2,%3}, [%4];"
        : "=r"(r[0]), "=r"(r[1]), "=r"(r[2]), "=r"(r[3]) : "r"(a));
}
__device__ __forceinline__ void ldsm_x2(uint32_t* r, uint32_t a) {
    asm volatile("ldmatrix.sync.aligned.m8n8.x2.shared.b16 {%0,%1}, [%2];"
        : "=r"(r[0]), "=r"(r[1]) : "r"(a));
}
__device__ __forceinline__ void mma_bf16(float* c, const uint32_t* a, const uint32_t* b) {
    asm volatile(
        "mma.sync.aligned.m16n8k16.row.col.f32.bf16.bf16.f32 "
        "{%0,%1,%2,%3}, {%4,%5,%6,%7}, {%8,%9}, {%0,%1,%2,%3};"
        : "+f"(c[0]), "+f"(c[1]), "+f"(c[2]), "+f"(c[3])
        : "r"(a[0]), "r"(a[1]), "r"(a[2]), "r"(a[3]), "r"(b[0]), "r"(b[1]));
}

// ---------------- prepass: split activations ----------------
__global__ __launch_bounds__(256) void split_act_kernel(
    const float* __restrict__ q, const float* __restrict__ k, const float* __restrict__ v,
    __nv_bfloat16* __restrict__ qh, __nv_bfloat16* __restrict__ ql,
    __nv_bfloat16* __restrict__ kh, __nv_bfloat16* __restrict__ kl,
    __nv_bfloat16* __restrict__ vh, __nv_bfloat16* __restrict__ vl)
{
    const int QE = MQ * DMODEL / 4;
    const int KE = MK * DMODEL / 4;
    int i = blockIdx.x * blockDim.x + threadIdx.x;
    const float* src; __nv_bfloat16 *dh, *dl;
    if (i < QE)               { src = q; dh = qh; dl = ql; }
    else if (i < QE + KE)     { src = k; dh = kh; dl = kl; i -= QE; }
    else if (i < QE + 2 * KE) { src = v; dh = vh; dl = vl; i -= QE + KE; }
    else return;
    float4 x = ((const float4*)src)[i];
    __nv_bfloat16 h0, h1, h2, h3, l0, l1, l2, l3;
    bf16_split(x.x, h0, l0); bf16_split(x.y, h1, l1);
    bf16_split(x.z, h2, l2); bf16_split(x.w, h3, l3);
    ((__nv_bfloat162*)dh)[i * 2 + 0] = __nv_bfloat162(h0, h1);
    ((__nv_bfloat162*)dh)[i * 2 + 1] = __nv_bfloat162(h2, h3);
    ((__nv_bfloat162*)dl)[i * 2 + 0] = __nv_bfloat162(l0, l1);
    ((__nv_bfloat162*)dl)[i * 2 + 1] = __nv_bfloat162(l2, l3);
}

// ---------------- prepass: transpose + split weights ----------------
__global__ __launch_bounds__(1024) void split_w_kernel(
    const float* __restrict__ W0, const float* __restrict__ W1,
    const float* __restrict__ W2, const float* __restrict__ W3,
    __nv_bfloat16* __restrict__ Wth, __nv_bfloat16* __restrict__ Wtl)
{
    __shared__ float t[32][33];
    const int z = blockIdx.z;
    const float* W = (z == 0) ? W0 : (z == 1) ? W1 : (z == 2) ? W2 : W3;
    const int n0 = blockIdx.x * 32, k0 = blockIdx.y * 32;
    const int tx = threadIdx.x, ty = threadIdx.y;
    t[ty][tx] = W[(size_t)(k0 + ty) * DMODEL + n0 + tx];
    __syncthreads();
    float x = t[tx][ty];
    __nv_bfloat16 h, l;
    bf16_split(x, h, l);
    size_t o = (size_t)z * DMODEL * DMODEL + (size_t)(n0 + ty) * DMODEL + k0 + tx;
    Wth[o] = h; Wtl[o] = l;
}

// ---------------- pipelined bf16x3 GEMM: C[128,128] = A[128,512] @ Bt[128,512]^T ------
// K-chunk 32, 80B padded rows (conflict-free ldsm), register prefetch of next chunk.
#define GROWB 80
#define GTSZ  (128 * GROWB)        // 10240 bytes per tile
#define NCH   16                   // 512 / 32

template<bool SPLIT>
__device__ __forceinline__ void gemm32_tile(
    const __nv_bfloat16* __restrict__ Ah, const __nv_bfloat16* __restrict__ Al,
    const __nv_bfloat16* __restrict__ Bh, const __nv_bfloat16* __restrict__ Bl,
    float* __restrict__ Cf, __nv_bfloat16* __restrict__ Ch, __nv_bfloat16* __restrict__ Cl,
    int row0, int col0)
{
    __shared__ char sm[4 * GTSZ];        // [Ah | Al | Bh | Bl]
    const uint32_t sb = smem_u32(sm);
    const int tid  = threadIdx.x;
    const int wid  = tid >> 5;
    const int lane = tid & 31;
    const int m0 = (wid & 1) * 64;
    const int n0 = (wid >> 1) * 32;

    float acc[4][4][4];
    #pragma unroll
    for (int mi = 0; mi < 4; mi++)
        #pragma unroll
        for (int ni = 0; ni < 4; ni++)
            #pragma unroll
            for (int e = 0; e < 4; e++) acc[mi][ni][e] = 0.0f;

    // per-thread chunk load coords: row r = tid>>1, bytes [(tid&1)*32, +32)
    const int lr  = tid >> 1;
    const int lcb = (tid & 1) * 32;
    const size_t gA = (size_t)(row0 + lr) * (DMODEL * 2) + lcb;   // byte offsets
    const size_t gB = (size_t)(col0 + lr) * (DMODEL * 2) + lcb;
    const uint32_t so = (uint32_t)lr * GROWB + lcb;

    const uint32_t a_base = sb + 0 * GTSZ + (uint32_t)(m0 + (lane & 15)) * GROWB + ((lane >> 4) << 4);
    const uint32_t b_base = sb + 2 * GTSZ + (uint32_t)(n0 + (lane & 7)) * GROWB + (((lane >> 3) & 1) << 4);

    uint4 pf[8];
    #pragma unroll
    for (int j = 0; j < 2; j++) {
        pf[0 + j] = *(const uint4*)((const char*)Ah + gA + j * 16);
        pf[2 + j] = *(const uint4*)((const char*)Al + gA + j * 16);
        pf[4 + j] = *(const uint4*)((const char*)Bh + gB + j * 16);
        pf[6 + j] = *(const uint4*)((const char*)Bl + gB + j * 16);
    }

    for (int ch = 0; ch < NCH; ch++) {
        #pragma unroll
        for (int j = 0; j < 2; j++) {
            *(uint4*)(sm + 0 * GTSZ + so + j * 16) = pf[0 + j];
            *(uint4*)(sm + 1 * GTSZ + so + j * 16) = pf[2 + j];
            *(uint4*)(sm + 2 * GTSZ + so + j * 16) = pf[4 + j];
            *(uint4*)(sm + 3 * GTSZ + so + j * 16) = pf[6 + j];
        }
        __syncthreads();

        if (ch + 1 < NCH) {
            const size_t kb = (size_t)(ch + 1) * 64;      // 32 bf16 = 64 bytes
            #pragma unroll
            for (int j = 0; j < 2; j++) {
                pf[0 + j] = *(const uint4*)((const char*)Ah + gA + kb + j * 16);
                pf[2 + j] = *(const uint4*)((const char*)Al + gA + kb + j * 16);
                pf[4 + j] = *(const uint4*)((const char*)Bh + gB + kb + j * 16);
                pf[6 + j] = *(const uint4*)((const char*)Bl + gB + kb + j * 16);
            }
        }

        #pragma unroll
        for (int ks = 0; ks < 2; ks++) {
            const uint32_t ko = (uint32_t)ks * 32;
            uint32_t af[4][4], b2[2];
            // phase 1: Ah terms (Ah*Bh, Ah*Bl)
            #pragma unroll
            for (int mi = 0; mi < 4; mi++)
                ldsm_x4(af[mi], a_base + (uint32_t)(mi * 16) * GROWB + ko);
            #pragma unroll
            for (int ni = 0; ni < 4; ni++) {
                const uint32_t bo = b_base + (uint32_t)(ni * 8) * GROWB + ko;
                ldsm_x2(b2, bo);
                #pragma unroll
                for (int mi = 0; mi < 4; mi++) mma_bf16(acc[mi][ni], af[mi], b2);
                ldsm_x2(b2, bo + GTSZ);
                #pragma unroll
                for (int mi = 0; mi < 4; mi++) mma_bf16(acc[mi][ni], af[mi], b2);
            }
            // phase 2: Al*Bh
            #pragma unroll
            for (int mi = 0; mi < 4; mi++)
                ldsm_x4(af[mi], a_base + GTSZ + (uint32_t)(mi * 16) * GROWB + ko);
            #pragma unroll
            for (int ni = 0; ni < 4; ni++) {
                ldsm_x2(b2, b_base + (uint32_t)(ni * 8) * GROWB + ko);
                #pragma unroll
                for (int mi = 0; mi < 4; mi++) mma_bf16(acc[mi][ni], af[mi], b2);
            }
        }
        __syncthreads();
    }

    // epilogue
    #pragma unroll
    for (int mi = 0; mi < 4; mi++) {
        #pragma unroll
        for (int ni = 0; ni < 4; ni++) {
            const int row = row0 + m0 + mi * 16 + (lane >> 2);
            const int col = col0 + n0 + ni * 8 + (lane & 3) * 2;
            const float* a = acc[mi][ni];
            if (SPLIT) {
                __nv_bfloat16 h0, h1, h2, h3, l0, l1, l2, l3;
                bf16_split(a[0], h0, l0); bf16_split(a[1], h1, l1);
                bf16_split(a[2], h2, l2); bf16_split(a[3], h3, l3);
                *(__nv_bfloat162*)&Ch[(size_t)row * DMODEL + col] = __nv_bfloat162(h0, h1);
                *(__nv_bfloat162*)&Cl[(size_t)row * DMODEL + col] = __nv_bfloat162(l0, l1);
                *(__nv_bfloat162*)&Ch[(size_t)(row + 8) * DMODEL + col] = __nv_bfloat162(h2, h3);
                *(__nv_bfloat162*)&Cl[(size_t)(row + 8) * DMODEL + col] = __nv_bfloat162(l2, l3);
            } else {
                *(float2*)&Cf[(size_t)row * DMODEL + col] = make_float2(a[0], a[1]);
                *(float2*)&Cf[(size_t)(row + 8) * DMODEL + col] = make_float2(a[2], a[3]);
            }
        }
    }
}

__global__ __launch_bounds__(256) void proj_fused_kernel(
    const __nv_bfloat16* __restrict__ qh, const __nv_bfloat16* __restrict__ ql,
    const __nv_bfloat16* __restrict__ kh, const __nv_bfloat16* __restrict__ kl,
    const __nv_bfloat16* __restrict__ vh, const __nv_bfloat16* __restrict__ vl,
    const __nv_bfloat16* __restrict__ Wth, const __nv_bfloat16* __restrict__ Wtl,
    __nv_bfloat16* __restrict__ Qph, __nv_bfloat16* __restrict__ Qpl,
    __nv_bfloat16* __restrict__ Kph, __nv_bfloat16* __restrict__ Kpl,
    __nv_bfloat16* __restrict__ Vph, __nv_bfloat16* __restrict__ Vpl)
{
    const int bid = blockIdx.x;
    const size_t WSZ = (size_t)DMODEL * DMODEL;
    const __nv_bfloat16 *Ah, *Al, *Bh, *Bl; __nv_bfloat16 *Ch, *Cl; int t;
    if (bid < 256)      { Ah = qh; Al = ql; Bh = Wth;           Bl = Wtl;           Ch = Qph; Cl = Qpl; t = bid; }
    else if (bid < 320) { Ah = kh; Al = kl; Bh = Wth + WSZ;     Bl = Wtl + WSZ;     Ch = Kph; Cl = Kpl; t = bid - 256; }
    else                { Ah = vh; Al = vl; Bh = Wth + 2 * WSZ; Bl = Wtl + 2 * WSZ; Ch = Vph; Cl = Vpl; t = bid - 320; }
    gemm32_tile<true>(Ah, Al, Bh, Bl, nullptr, Ch, Cl, (t >> 2) * 128, (t & 3) * 128);
}

__global__ __launch_bounds__(256) void outproj_kernel(
    const __nv_bfloat16* __restrict__ ch, const __nv_bfloat16* __restrict__ cl,
    const __nv_bfloat16* __restrict__ Wth, const __nv_bfloat16* __restrict__ Wtl,
    float* __restrict__ out)
{
    const size_t WSZ = (size_t)DMODEL * DMODEL;
    gemm32_tile<false>(ch, cl, Wth + 3 * WSZ, Wtl + 3 * WSZ, out, nullptr, nullptr,
                       blockIdx.y * 128, blockIdx.x * 128);
}

// ---------------- tensor-core sparse attention ----------------
// CTA = (64 queries, head, batch), 128 threads = 4 warps; warp w owns rows 16w..16w+15.
// S[64x32] = Q @ Kwin^T (bf16x3, masked), P = softmax rows, O[64x64] = P @ Vwin (bf16x3).
#define AROWB 144                   // Q/K rows: 64 bf16 = 128B + pad
#define VROWB 80                    // V^T rows: 32 bf16 = 64B + pad
#define SQH 0
#define SQL (SQH + 64 * AROWB)      // 9216
#define SKH (SQL + 64 * AROWB)      // 18432
#define SKL (SKH + 32 * AROWB)      // 23040
#define SVH (SKL + 32 * AROWB)      // 27648
#define SVL (SVH + 64 * VROWB)      // 32768
#define ATT_SM (SVL + 64 * VROWB)   // 37888

__global__ __launch_bounds__(128) void attn_tc_kernel(
    const __nv_bfloat16* __restrict__ Qph, const __nv_bfloat16* __restrict__ Qpl,
    const __nv_bfloat16* __restrict__ Kph, const __nv_bfloat16* __restrict__ Kpl,
    const __nv_bfloat16* __restrict__ Vph, const __nv_bfloat16* __restrict__ Vpl,
    __nv_bfloat16* __restrict__ ctxh, __nv_bfloat16* __restrict__ ctxl)
{
    __shared__ char sm[ATT_SM];
    const uint32_t sb = smem_u32(sm);
    const int c0  = blockIdx.x * 64;
    const int h   = blockIdx.y;
    const int b   = blockIdx.z;
    const int tid = threadIdx.x;
    const int wid = tid >> 5;
    const int lane = tid & 31;

    int jmin = (c0 - (SPAN - 1) + (STRIDE - 1)) >> 2;   // ceil((c0-63)/4)
    if (jmin < 0) jmin = 0;
    int jmax = (c0 + 63) >> 2;
    if (jmax > LKV - 1) jmax = LKV - 1;
    const int nrows = jmax - jmin + 1;                  // <= 32

    // zero K + V regions (rows beyond nrows must be harmless)
    for (int i = tid; i < (ATT_SM - SKH) / 4; i += 128)
        ((uint32_t*)(sm + SKH))[i] = 0;

    // load Q tile (64 rows x 128B), hi and lo
    for (int u = tid; u < 512; u += 128) {
        const int r = u >> 3, cb = (u & 7) << 4;
        const size_t gb = (size_t)(b * LQ + c0 + r) * (DMODEL * 2) + h * DHEAD * 2 + cb;
        *(uint4*)(sm + SQH + r * AROWB + cb) = *(const uint4*)((const char*)Qph + gb);
        *(uint4*)(sm + SQL + r * AROWB + cb) = *(const uint4*)((const char*)Qpl + gb);
    }
    // load K window rows
    for (int u = tid; u < nrows * 8; u += 128) {
        const int r = u >> 3, cb = (u & 7) << 4;
        const size_t gb = (size_t)(b * LKV + jmin + r) * (DMODEL * 2) + h * DHEAD * 2 + cb;
        *(uint4*)(sm + SKH + r * AROWB + cb) = *(const uint4*)((const char*)Kph + gb);
        *(uint4*)(sm + SKL + r * AROWB + cb) = *(const uint4*)((const char*)Kpl + gb);
    }
    __syncthreads();   // V-transpose writes below scatter; keep zero-fill ordered first
    // load V window transposed: Vt[d][win]
    for (int u = tid; u < nrows * 8; u += 128) {
        const int r = u >> 3, d0 = (u & 7) << 3;
        const size_t gb = (size_t)(b * LKV + jmin + r) * (DMODEL * 2) + h * DHEAD * 2 + d0 * 2;
        uint4 vh4 = *(const uint4*)((const char*)Vph + gb);
        uint4 vl4 = *(const uint4*)((const char*)Vpl + gb);
        const uint32_t wh[4] = {vh4.x, vh4.y, vh4.z, vh4.w};
        const uint32_t wl[4] = {vl4.x, vl4.y, vl4.z, vl4.w};
        #pragma unroll
        for (int j = 0; j < 8; j++) {
            const uint16_t eh = (uint16_t)(wh[j >> 1] >> ((j & 1) * 16));
            const uint16_t el = (uint16_t)(wl[j >> 1] >> ((j & 1) * 16));
            *(uint16_t*)(sm + SVH + (d0 + j) * VROWB + r * 2) = eh;
            *(uint16_t*)(sm + SVL + (d0 + j) * VROWB + r * 2) = el;
        }
    }
    __syncthreads();

    // ---- S = Q @ K^T  (16 rows per warp, 32 cols) ----
    float s[4][4];
    #pragma unroll
    for (int ni = 0; ni < 4; ni++)
        #pragma unroll
        for (int e = 0; e < 4; e++) s[ni][e] = 0.0f;

    const uint32_t qa = sb + (uint32_t)(wid * 16 + (lane & 15)) * AROWB + ((lane >> 4) << 4);
    const uint32_t kb = sb + SKH + (uint32_t)(lane & 7) * AROWB + (((lane >> 3) & 1) << 4);
    #pragma unroll
    for (int ks = 0; ks < 4; ks++) {
        const uint32_t ko = (uint32_t)ks * 32;
        uint32_t qh4[4], ql4[4], b2[2];
        ldsm_x4(qh4, qa + SQH + ko);
        ldsm_x4(ql4, qa + SQL + ko);
        #pragma unroll
        for (int ni = 0; ni < 4; ni++) {
            const uint32_t bo = kb + (uint32_t)(ni * 8) * AROWB + ko;
            ldsm_x2(b2, bo);
            mma_bf16(s[ni], qh4, b2);
            mma_bf16(s[ni], ql4, b2);          // Ql*Kh
            ldsm_x2(b2, bo + (SKL - SKH));
            mma_bf16(s[ni], qh4, b2);          // Qh*Kl
        }
    }

    // ---- mask + scale ----
    const int r_lo = c0 + wid * 16 + (lane >> 2);
    const int r_hi = r_lo + 8;
    #pragma unroll
    for (int ni = 0; ni < 4; ni++) {
        #pragma unroll
        for (int e = 0; e < 4; e++) {
            const int col_abs = jmin + ni * 8 + (lane & 3) * 2 + (e & 1);
            const int c = (e < 2) ? r_lo : r_hi;
            const bool valid = (unsigned)(c - 4 * col_abs) < (unsigned)SPAN;
            s[ni][e] = valid ? s[ni][e] * 0.125f : -1e30f;
        }
    }

    // ---- softmax (rows r_lo: e=0,1 ; r_hi: e=2,3), reduction over 4-lane quad ----
    float mx0 = -1e30f, mx1 = -1e30f;
    #pragma unroll
    for (int ni = 0; ni < 4; ni++) {
        mx0 = fmaxf(mx0, fmaxf(s[ni][0], s[ni][1]));
        mx1 = fmaxf(mx1, fmaxf(s[ni][2], s[ni][3]));
    }
    mx0 = fmaxf(mx0, __shfl_xor_sync(0xffffffffu, mx0, 1));
    mx0 = fmaxf(mx0, __shfl_xor_sync(0xffffffffu, mx0, 2));
    mx1 = fmaxf(mx1, __shfl_xor_sync(0xffffffffu, mx1, 1));
    mx1 = fmaxf(mx1, __shfl_xor_sync(0xffffffffu, mx1, 2));
    float sum0 = 0.0f, sum1 = 0.0f;
    #pragma unroll
    for (int ni = 0; ni < 4; ni++) {
        s[ni][0] = __expf(s[ni][0] - mx0); sum0 += s[ni][0];
        s[ni][1] = __expf(s[ni][1] - mx0); sum0 += s[ni][1];
        s[ni][2] = __expf(s[ni][2] - mx1); sum1 += s[ni][2];
        s[ni][3] = __expf(s[ni][3] - mx1); sum1 += s[ni][3];
    }
    sum0 += __shfl_xor_sync(0xffffffffu, sum0, 1);
    sum0 += __shfl_xor_sync(0xffffffffu, sum0, 2);
    sum1 += __shfl_xor_sync(0xffffffffu, sum1, 1);
    sum1 += __shfl_xor_sync(0xffffffffu, sum1, 2);
    const float inv0 = 1.0f / sum0, inv1 = 1.0f / sum1;
    #pragma unroll
    for (int ni = 0; ni < 4; ni++) {
        s[ni][0] *= inv0; s[ni][1] *= inv0;
        s[ni][2] *= inv1; s[ni][3] *= inv1;
    }

    // ---- pack P into A-frags (hi + lo) ----
    uint32_t aPh[2][4], aPl[2][4];
    #pragma unroll
    for (int kc = 0; kc < 2; kc++) {
        #pragma unroll
        for (int half = 0; half < 2; half++) {
            const float* p = s[2 * kc + half];
            float lo0 = p[0] - __bfloat162float(__float2bfloat16_rn(p[0]));
            float lo1 = p[1] - __bfloat162float(__float2bfloat16_rn(p[1]));
            float lo2 = p[2] - __bfloat162float(__float2bfloat16_rn(p[2]));
            float lo3 = p[3] - __bfloat162float(__float2bfloat16_rn(p[3]));
            aPh[kc][half * 2 + 0] = pack_bf2(p[0], p[1]);
            aPh[kc][half * 2 + 1] = pack_bf2(p[2], p[3]);
            aPl[kc][half * 2 + 0] = pack_bf2(lo0, lo1);
            aPl[kc][half * 2 + 1] = pack_bf2(lo2, lo3);
        }
    }
    // frag order fix: a0=(r,k0),(r,k1); a1=(r+8,k0),(r+8,k1); a2=(r,k8)... built above as
    // [kc][0]=rows-lo of ni=2kc, [1]=rows-hi of ni=2kc, [2]=rows-lo of ni=2kc+1, [3]=rows-hi.
    // That matches {a0,a1,a2,a3} = {(r,k),( r+8,k),(r,k+8),(r+8,k+8)} layout.

    // ---- O = P @ V^T-frags ----
    float o[8][4];
    #pragma unroll
    for (int ni = 0; ni < 8; ni++)
        #pragma unroll
        for (int e = 0; e < 4; e++) o[ni][e] = 0.0f;
    const uint32_t vb = sb + SVH + (uint32_t)(lane & 7) * VROWB + (((lane >> 3) & 1) << 4);
    #pragma unroll
    for (int kc = 0; kc < 2; kc++) {
        const uint32_t ko = (uint32_t)kc * 32;
        #pragma unroll
        for (int ni = 0; ni < 8; ni++) {
            uint32_t b2[2];
            const uint32_t bo = vb + (uint32_t)(ni * 8) * VROWB + ko;
            ldsm_x2(b2, bo);
            mma_bf16(o[ni], aPh[kc], b2);
            mma_bf16(o[ni], aPl[kc], b2);      // Pl*Vh
            ldsm_x2(b2, bo + (SVL - SVH));
            mma_bf16(o[ni], aPh[kc], b2);      // Ph*Vl
        }
    }

    // ---- store ctx hi/lo ----
    #pragma unroll
    for (int ni = 0; ni < 8; ni++) {
        const int col = ni * 8 + (lane & 3) * 2;
        const size_t i0 = (size_t)(b * LQ + r_lo) * DMODEL + h * DHEAD + col;
        const size_t i1 = (size_t)(b * LQ + r_hi) * DMODEL + h * DHEAD + col;
        __nv_bfloat16 h0, h1, h2, h3, l0, l1, l2, l3;
        bf16_split(o[ni][0], h0, l0); bf16_split(o[ni][1], h1, l1);
        bf16_split(o[ni][2], h2, l2); bf16_split(o[ni][3], h3, l3);
        *(__nv_bfloat162*)&ctxh[i0] = __nv_bfloat162(h0, h1);
        *(__nv_bfloat162*)&ctxl[i0] = __nv_bfloat162(l0, l1);
        *(__nv_bfloat162*)&ctxh[i1] = __nv_bfloat162(h2, h3);
        *(__nv_bfloat162*)&ctxl[i1] = __nv_bfloat162(l2, l3);
    }
}

// ---------------- launch ----------------
extern "C" void kernel_launch(void* const* d_in, const int* in_sizes, int n_in,
                              void* d_out, int out_size)
{
    const float* q    = (const float*)d_in[0];
    const float* k    = (const float*)d_in[1];
    const float* v    = (const float*)d_in[2];
    const float* Wq   = (const float*)d_in[3];
    const float* Wk   = (const float*)d_in[4];
    const float* Wv   = (const float*)d_in[5];
    const float* Wout = (const float*)d_in[6];
    float* out = (float*)d_out;

    __nv_bfloat16 *qh, *ql, *kh, *kl, *vh, *vl;
    __nv_bfloat16 *Qph, *Qpl, *Kph, *Kpl, *Vph, *Vpl, *ch, *cl, *Wth, *Wtl;
    cudaGetSymbolAddress((void**)&qh,  g_qh);  cudaGetSymbolAddress((void**)&ql,  g_ql);
    cudaGetSymbolAddress((void**)&kh,  g_kh);  cudaGetSymbolAddress((void**)&kl,  g_kl);
    cudaGetSymbolAddress((void**)&vh,  g_vh);  cudaGetSymbolAddress((void**)&vl,  g_vl);
    cudaGetSymbolAddress((void**)&Qph, g_Qph); cudaGetSymbolAddress((void**)&Qpl, g_Qpl);
    cudaGetSymbolAddress((void**)&Kph, g_Kph); cudaGetSymbolAddress((void**)&Kpl, g_Kpl);
    cudaGetSymbolAddress((void**)&Vph, g_Vph); cudaGetSymbolAddress((void**)&Vpl, g_Vpl);
    cudaGetSymbolAddress((void**)&ch,  g_ch);  cudaGetSymbolAddress((void**)&cl,  g_cl);
    cudaGetSymbolAddress((void**)&Wth, g_Wth); cudaGetSymbolAddress((void**)&Wtl, g_Wtl);

    const int totalV = (MQ * DMODEL + 2 * MK * DMODEL) / 4;
    split_act_kernel<<<(totalV + 255) / 256, 256>>>(q, k, v, qh, ql, kh, kl, vh, vl);
    split_w_kernel<<<dim3(16, 16, 4), dim3(32, 32)>>>(Wq, Wk, Wv, Wout, Wth, Wtl);
    proj_fused_kernel<<<384, 256>>>(qh, ql, kh, kl, vh, vl, Wth, Wtl,
                                    Qph, Qpl, Kph, Kpl, Vph, Vpl);
    attn_tc_kernel<<<dim3(LQ / 64, HEADS, B_SZ), 128>>>(Qph, Qpl, Kph, Kpl, Vph, Vpl, ch, cl);
    outproj_kernel<<<dim3(4, 64), 256>>>(ch, cl, Wth, Wtl, out);
}

// round 6
// speedup vs baseline: 1.2601x; 1.2601x over previous
#include <cuda_runtime.h>
#include <cuda_bf16.h>
#include <cstdint>

#define B_SZ   2
#define LQ     4096
#define LKV    1024
#define DMODEL 512
#define HEADS  8
#define DHEAD  64
#define SPAN   64
#define STRIDE 4

#define MQ (B_SZ * LQ)    // 8192
#define MK (B_SZ * LKV)   // 2048

// ---------------- scratch ----------------
__device__ __nv_bfloat16 g_qh[MQ * DMODEL], g_ql[MQ * DMODEL];
__device__ __nv_bfloat16 g_kh[MK * DMODEL], g_kl[MK * DMODEL];
__device__ __nv_bfloat16 g_vh[MK * DMODEL], g_vl[MK * DMODEL];
__device__ __nv_bfloat16 g_Qph[MQ * DMODEL], g_Qpl[MQ * DMODEL];
__device__ __nv_bfloat16 g_Kph[MK * DMODEL], g_Kpl[MK * DMODEL];
__device__ __nv_bfloat16 g_Vph[MK * DMODEL], g_Vpl[MK * DMODEL];
__device__ __nv_bfloat16 g_ch[MQ * DMODEL], g_cl[MQ * DMODEL];
__device__ __nv_bfloat16 g_Wth[4 * DMODEL * DMODEL], g_Wtl[4 * DMODEL * DMODEL];

// ---------------- helpers ----------------
__device__ __forceinline__ uint32_t smem_u32(const void* p) {
    uint32_t a;
    asm("{ .reg .u64 t; cvta.to.shared.u64 t, %1; cvt.u32.u64 %0, t; }" : "=r"(a) : "l"(p));
    return a;
}
__device__ __forceinline__ void bf16_split(float x, __nv_bfloat16& h, __nv_bfloat16& l) {
    h = __float2bfloat16_rn(x);
    l = __float2bfloat16_rn(x - __bfloat162float(h));
}
__device__ __forceinline__ uint32_t pack_bf2(float a, float b) {
    __nv_bfloat162 t(__float2bfloat16_rn(a), __float2bfloat16_rn(b));
    return *(uint32_t*)&t;
}
__device__ __forceinline__ void ldsm_x4(uint32_t* r, uint32_t a) {
    asm volatile("ldmatrix.sync.aligned.m8n8.x4.shared.b16 {%0,%1,%2,%3}, [%4];"
        : "=r"(r[0]), "=r"(r[1]), "=r"(r[2]), "=r"(r[3]) : "r"(a));
}
__device__ __forceinline__ void ldsm_x2(uint32_t* r, uint32_t a) {
    asm volatile("ldmatrix.sync.aligned.m8n8.x2.shared.b16 {%0,%1}, [%2];"
        : "=r"(r[0]), "=r"(r[1]) : "r"(a));
}
__device__ __forceinline__ void ldsm_x2_trans(uint32_t* r, uint32_t a) {
    asm volatile("ldmatrix.sync.aligned.m8n8.x2.trans.shared.b16 {%0,%1}, [%2];"
        : "=r"(r[0]), "=r"(r[1]) : "r"(a));
}
__device__ __forceinline__ void mma_bf16(float* c, const uint32_t* a, const uint32_t* b) {
    asm volatile(
        "mma.sync.aligned.m16n8k16.row.col.f32.bf16.bf16.f32 "
        "{%0,%1,%2,%3}, {%4,%5,%6,%7}, {%8,%9}, {%0,%1,%2,%3};"
        : "+f"(c[0]), "+f"(c[1]), "+f"(c[2]), "+f"(c[3])
        : "r"(a[0]), "r"(a[1]), "r"(a[2]), "r"(a[3]), "r"(b[0]), "r"(b[1]));
}
__device__ __forceinline__ void cp16(uint32_t dst, const void* src) {
    asm volatile("cp.async.cg.shared.global [%0], [%1], 16;" :: "r"(dst), "l"(src));
}
#define CP_COMMIT() asm volatile("cp.async.commit_group;" ::: "memory")
#define CP_WAIT0()  asm volatile("cp.async.wait_group 0;" ::: "memory")

// ---------------- prepass: split activations ----------------
__global__ __launch_bounds__(256) void split_act_kernel(
    const float* __restrict__ q, const float* __restrict__ k, const float* __restrict__ v,
    __nv_bfloat16* __restrict__ qh, __nv_bfloat16* __restrict__ ql,
    __nv_bfloat16* __restrict__ kh, __nv_bfloat16* __restrict__ kl,
    __nv_bfloat16* __restrict__ vh, __nv_bfloat16* __restrict__ vl)
{
    const int QE = MQ * DMODEL / 4;
    const int KE = MK * DMODEL / 4;
    int i = blockIdx.x * blockDim.x + threadIdx.x;
    const float* src; __nv_bfloat16 *dh, *dl;
    if (i < QE)               { src = q; dh = qh; dl = ql; }
    else if (i < QE + KE)     { src = k; dh = kh; dl = kl; i -= QE; }
    else if (i < QE + 2 * KE) { src = v; dh = vh; dl = vl; i -= QE + KE; }
    else return;
    float4 x = ((const float4*)src)[i];
    __nv_bfloat16 h0, h1, h2, h3, l0, l1, l2, l3;
    bf16_split(x.x, h0, l0); bf16_split(x.y, h1, l1);
    bf16_split(x.z, h2, l2); bf16_split(x.w, h3, l3);
    ((__nv_bfloat162*)dh)[i * 2 + 0] = __nv_bfloat162(h0, h1);
    ((__nv_bfloat162*)dh)[i * 2 + 1] = __nv_bfloat162(h2, h3);
    ((__nv_bfloat162*)dl)[i * 2 + 0] = __nv_bfloat162(l0, l1);
    ((__nv_bfloat162*)dl)[i * 2 + 1] = __nv_bfloat162(l2, l3);
}

// ---------------- prepass: transpose + split weights ----------------
__global__ __launch_bounds__(1024) void split_w_kernel(
    const float* __restrict__ W0, const float* __restrict__ W1,
    const float* __restrict__ W2, const float* __restrict__ W3,
    __nv_bfloat16* __restrict__ Wth, __nv_bfloat16* __restrict__ Wtl)
{
    __shared__ float t[32][33];
    const int z = blockIdx.z;
    const float* W = (z == 0) ? W0 : (z == 1) ? W1 : (z == 2) ? W2 : W3;
    const int n0 = blockIdx.x * 32, k0 = blockIdx.y * 32;
    const int tx = threadIdx.x, ty = threadIdx.y;
    t[ty][tx] = W[(size_t)(k0 + ty) * DMODEL + n0 + tx];
    __syncthreads();
    float x = t[tx][ty];
    __nv_bfloat16 h, l;
    bf16_split(x, h, l);
    size_t o = (size_t)z * DMODEL * DMODEL + (size_t)(n0 + ty) * DMODEL + k0 + tx;
    Wth[o] = h; Wtl[o] = l;
}

// ---------------- cp.async double-buffered bf16x3 GEMM ----------------
// C[128,128] = A[128,512] @ Bt[128,512]^T ; K-chunk 32, 80B rows, 2 stages.
#define GROWB 80
#define GTSZ  (128 * GROWB)        // 10240
#define STG   (4 * GTSZ)           // 40960 bytes per stage
#define GEMM_SMEM (2 * STG)        // 81920
#define NCH   16                   // 512 / 32

template<bool SPLIT>
__device__ __forceinline__ void gemm_pipe_tile(
    const __nv_bfloat16* __restrict__ Ah, const __nv_bfloat16* __restrict__ Al,
    const __nv_bfloat16* __restrict__ Bh, const __nv_bfloat16* __restrict__ Bl,
    float* __restrict__ Cf, __nv_bfloat16* __restrict__ Ch, __nv_bfloat16* __restrict__ Cl,
    int row0, int col0)
{
    extern __shared__ char sm[];
    const uint32_t sb = smem_u32(sm);
    const int tid  = threadIdx.x;
    const int wid  = tid >> 5;
    const int lane = tid & 31;
    const int m0 = (wid & 1) * 64;
    const int n0 = (wid >> 1) * 32;

    float acc[4][4][4];
    #pragma unroll
    for (int mi = 0; mi < 4; mi++)
        #pragma unroll
        for (int ni = 0; ni < 4; ni++)
            #pragma unroll
            for (int e = 0; e < 4; e++) acc[mi][ni][e] = 0.0f;

    // per-lane ldsm offsets (within a tile)
    const uint32_t a_off = (uint32_t)(m0 + (lane & 15)) * GROWB + ((lane >> 4) << 4);
    const uint32_t b_off = (uint32_t)((lane & 7) + ((lane >> 4) & 1) * 8) * GROWB
                         + (((lane >> 3) & 1) << 4);

    // stage-issue coords: 512 x 16B ops per tile pair, 2 iterations / thread
    const int ir0 = (tid + 0)   >> 2, ic0 = ((tid + 0)   & 3) << 4;
    const int ir1 = (tid + 256) >> 2, ic1 = ((tid + 256) & 3) << 4;

    auto issue_stage = [&](int ch, int buf) {
        const uint32_t stg = sb + (uint32_t)buf * STG;
        const size_t kb = (size_t)ch * 64;      // chunk byte offset in K
        {
            const uint32_t dso = (uint32_t)ir0 * GROWB + ic0;
            const size_t ga = (size_t)(row0 + ir0) * (DMODEL * 2) + kb + ic0;
            const size_t gb = (size_t)(col0 + ir0) * (DMODEL * 2) + kb + ic0;
            cp16(stg + 0 * GTSZ + dso, (const char*)Ah + ga);
            cp16(stg + 1 * GTSZ + dso, (const char*)Al + ga);
            cp16(stg + 2 * GTSZ + dso, (const char*)Bh + gb);
            cp16(stg + 3 * GTSZ + dso, (const char*)Bl + gb);
        }
        {
            const uint32_t dso = (uint32_t)ir1 * GROWB + ic1;
            const size_t ga = (size_t)(row0 + ir1) * (DMODEL * 2) + kb + ic1;
            const size_t gb = (size_t)(col0 + ir1) * (DMODEL * 2) + kb + ic1;
            cp16(stg + 0 * GTSZ + dso, (const char*)Ah + ga);
            cp16(stg + 1 * GTSZ + dso, (const char*)Al + ga);
            cp16(stg + 2 * GTSZ + dso, (const char*)Bh + gb);
            cp16(stg + 3 * GTSZ + dso, (const char*)Bl + gb);
        }
        CP_COMMIT();
    };

    issue_stage(0, 0);

    for (int ch = 0; ch < NCH; ch++) {
        CP_WAIT0();
        __syncthreads();                         // stage ch ready; compute(ch-1) done by all
        if (ch + 1 < NCH) issue_stage(ch + 1, (ch + 1) & 1);

        const uint32_t stg = sb + (uint32_t)(ch & 1) * STG;
        const uint32_t aH = stg + 0 * GTSZ + a_off;
        const uint32_t aL = stg + 1 * GTSZ + a_off;
        const uint32_t bH = stg + 2 * GTSZ + b_off + (uint32_t)n0 * GROWB;
        const uint32_t bL = stg + 3 * GTSZ + b_off + (uint32_t)n0 * GROWB;

        #pragma unroll
        for (int ks = 0; ks < 2; ks++) {
            const uint32_t ko = (uint32_t)ks * 32;
            uint32_t ah[4][4], al[4][4];
            #pragma unroll
            for (int mi = 0; mi < 4; mi++) {
                ldsm_x4(ah[mi], aH + (uint32_t)(mi * 16) * GROWB + ko);
                ldsm_x4(al[mi], aL + (uint32_t)(mi * 16) * GROWB + ko);
            }
            #pragma unroll
            for (int nj = 0; nj < 2; nj++) {
                uint32_t bh4[4], bl4[4];
                const uint32_t bno = (uint32_t)(nj * 16) * GROWB + ko;
                ldsm_x4(bh4, bH + bno);
                ldsm_x4(bl4, bL + bno);
                #pragma unroll
                for (int mi = 0; mi < 4; mi++) {
                    mma_bf16(acc[mi][2 * nj + 0], ah[mi], bh4 + 0);
                    mma_bf16(acc[mi][2 * nj + 0], al[mi], bh4 + 0);
                    mma_bf16(acc[mi][2 * nj + 0], ah[mi], bl4 + 0);
                    mma_bf16(acc[mi][2 * nj + 1], ah[mi], bh4 + 2);
                    mma_bf16(acc[mi][2 * nj + 1], al[mi], bh4 + 2);
                    mma_bf16(acc[mi][2 * nj + 1], ah[mi], bl4 + 2);
                }
            }
        }
    }

    // epilogue
    #pragma unroll
    for (int mi = 0; mi < 4; mi++) {
        #pragma unroll
        for (int ni = 0; ni < 4; ni++) {
            const int row = row0 + m0 + mi * 16 + (lane >> 2);
            const int col = col0 + n0 + ni * 8 + (lane & 3) * 2;
            const float* a = acc[mi][ni];
            if (SPLIT) {
                __nv_bfloat16 h0, h1, h2, h3, l0, l1, l2, l3;
                bf16_split(a[0], h0, l0); bf16_split(a[1], h1, l1);
                bf16_split(a[2], h2, l2); bf16_split(a[3], h3, l3);
                *(__nv_bfloat162*)&Ch[(size_t)row * DMODEL + col] = __nv_bfloat162(h0, h1);
                *(__nv_bfloat162*)&Cl[(size_t)row * DMODEL + col] = __nv_bfloat162(l0, l1);
                *(__nv_bfloat162*)&Ch[(size_t)(row + 8) * DMODEL + col] = __nv_bfloat162(h2, h3);
                *(__nv_bfloat162*)&Cl[(size_t)(row + 8) * DMODEL + col] = __nv_bfloat162(l2, l3);
            } else {
                *(float2*)&Cf[(size_t)row * DMODEL + col] = make_float2(a[0], a[1]);
                *(float2*)&Cf[(size_t)(row + 8) * DMODEL + col] = make_float2(a[2], a[3]);
            }
        }
    }
}

__global__ __launch_bounds__(256, 2) void proj_fused_kernel(
    const __nv_bfloat16* __restrict__ qh, const __nv_bfloat16* __restrict__ ql,
    const __nv_bfloat16* __restrict__ kh, const __nv_bfloat16* __restrict__ kl,
    const __nv_bfloat16* __restrict__ vh, const __nv_bfloat16* __restrict__ vl,
    const __nv_bfloat16* __restrict__ Wth, const __nv_bfloat16* __restrict__ Wtl,
    __nv_bfloat16* __restrict__ Qph, __nv_bfloat16* __restrict__ Qpl,
    __nv_bfloat16* __restrict__ Kph, __nv_bfloat16* __restrict__ Kpl,
    __nv_bfloat16* __restrict__ Vph, __nv_bfloat16* __restrict__ Vpl)
{
    const int bid = blockIdx.x;
    const size_t WSZ = (size_t)DMODEL * DMODEL;
    const __nv_bfloat16 *Ah, *Al, *Bh, *Bl; __nv_bfloat16 *Ch, *Cl; int t;
    if (bid < 256)      { Ah = qh; Al = ql; Bh = Wth;           Bl = Wtl;           Ch = Qph; Cl = Qpl; t = bid; }
    else if (bid < 320) { Ah = kh; Al = kl; Bh = Wth + WSZ;     Bl = Wtl + WSZ;     Ch = Kph; Cl = Kpl; t = bid - 256; }
    else                { Ah = vh; Al = vl; Bh = Wth + 2 * WSZ; Bl = Wtl + 2 * WSZ; Ch = Vph; Cl = Vpl; t = bid - 320; }
    gemm_pipe_tile<true>(Ah, Al, Bh, Bl, nullptr, Ch, Cl, (t >> 2) * 128, (t & 3) * 128);
}

__global__ __launch_bounds__(256, 2) void outproj_kernel(
    const __nv_bfloat16* __restrict__ ch, const __nv_bfloat16* __restrict__ cl,
    const __nv_bfloat16* __restrict__ Wth, const __nv_bfloat16* __restrict__ Wtl,
    float* __restrict__ out)
{
    const size_t WSZ = (size_t)DMODEL * DMODEL;
    gemm_pipe_tile<false>(ch, cl, Wth + 3 * WSZ, Wtl + 3 * WSZ, out, nullptr, nullptr,
                          blockIdx.y * 128, blockIdx.x * 128);
}

// ---------------- tensor-core sparse attention ----------------
// CTA = 64 queries x (head, batch); 4 warps; V row-major + ldmatrix.trans.
#define AROWB 144
#define SQH 0
#define SQL (SQH + 64 * AROWB)      // 9216
#define SKH (SQL + 64 * AROWB)      // 18432
#define SKL (SKH + 32 * AROWB)      // 23040
#define SVH (SKL + 32 * AROWB)      // 27648
#define SVL (SVH + 32 * AROWB)      // 32256
#define ATT_SM (SVL + 32 * AROWB)   // 36864

__global__ __launch_bounds__(128) void attn_tc_kernel(
    const __nv_bfloat16* __restrict__ Qph, const __nv_bfloat16* __restrict__ Qpl,
    const __nv_bfloat16* __restrict__ Kph, const __nv_bfloat16* __restrict__ Kpl,
    const __nv_bfloat16* __restrict__ Vph, const __nv_bfloat16* __restrict__ Vpl,
    __nv_bfloat16* __restrict__ ctxh, __nv_bfloat16* __restrict__ ctxl)
{
    __shared__ char sm[ATT_SM];
    const uint32_t sb = smem_u32(sm);
    const int c0  = blockIdx.x * 64;
    const int h   = blockIdx.y;
    const int b   = blockIdx.z;
    const int tid = threadIdx.x;
    const int wid = tid >> 5;
    const int lane = tid & 31;

    int jmin = (c0 - (SPAN - 1) + (STRIDE - 1)) >> 2;
    if (jmin < 0) jmin = 0;
    int jmax = (c0 + 63) >> 2;
    if (jmax > LKV - 1) jmax = LKV - 1;
    const int nrows = jmax - jmin + 1;                  // <= 32

    // zero V tail rows (weight-0 rows must not be NaN)
    for (int u = tid; u < (32 - nrows) * 36; u += 128) {
        const int r = nrows + u / 36, w = u % 36;
        ((uint32_t*)(sm + SVH))[r * 36 + w] = 0;
        ((uint32_t*)(sm + SVL))[r * 36 + w] = 0;
    }
    // Q tile (64 rows x 128B)
    for (int u = tid; u < 512; u += 128) {
        const int r = u >> 3, cb = (u & 7) << 4;
        const size_t gb = (size_t)(b * LQ + c0 + r) * (DMODEL * 2) + h * DHEAD * 2 + cb;
        *(uint4*)(sm + SQH + r * AROWB + cb) = *(const uint4*)((const char*)Qph + gb);
        *(uint4*)(sm + SQL + r * AROWB + cb) = *(const uint4*)((const char*)Qpl + gb);
    }
    // K + V window rows (row-major)
    for (int u = tid; u < nrows * 8; u += 128) {
        const int r = u >> 3, cb = (u & 7) << 4;
        const size_t gb = (size_t)(b * LKV + jmin + r) * (DMODEL * 2) + h * DHEAD * 2 + cb;
        *(uint4*)(sm + SKH + r * AROWB + cb) = *(const uint4*)((const char*)Kph + gb);
        *(uint4*)(sm + SKL + r * AROWB + cb) = *(const uint4*)((const char*)Kpl + gb);
        *(uint4*)(sm + SVH + r * AROWB + cb) = *(const uint4*)((const char*)Vph + gb);
        *(uint4*)(sm + SVL + r * AROWB + cb) = *(const uint4*)((const char*)Vpl + gb);
    }
    __syncthreads();

    // ---- S = Q @ K^T ----
    float s[4][4];
    #pragma unroll
    for (int ni = 0; ni < 4; ni++)
        #pragma unroll
        for (int e = 0; e < 4; e++) s[ni][e] = 0.0f;

    const uint32_t qa = sb + (uint32_t)(wid * 16 + (lane & 15)) * AROWB + ((lane >> 4) << 4);
    const uint32_t kb = sb + SKH + (uint32_t)(lane & 7) * AROWB + (((lane >> 3) & 1) << 4);
    #pragma unroll
    for (int ks = 0; ks < 4; ks++) {
        const uint32_t ko = (uint32_t)ks * 32;
        uint32_t qh4[4], ql4[4], b2[2];
        ldsm_x4(qh4, qa + SQH + ko);
        ldsm_x4(ql4, qa + SQL + ko);
        #pragma unroll
        for (int ni = 0; ni < 4; ni++) {
            const uint32_t bo = kb + (uint32_t)(ni * 8) * AROWB + ko;
            ldsm_x2(b2, bo);
            mma_bf16(s[ni], qh4, b2);
            mma_bf16(s[ni], ql4, b2);
            ldsm_x2(b2, bo + (SKL - SKH));
            mma_bf16(s[ni], qh4, b2);
        }
    }

    // ---- mask + scale ----
    const int r_lo = c0 + wid * 16 + (lane >> 2);
    const int r_hi = r_lo + 8;
    #pragma unroll
    for (int ni = 0; ni < 4; ni++) {
        #pragma unroll
        for (int e = 0; e < 4; e++) {
            const int col_abs = jmin + ni * 8 + (lane & 3) * 2 + (e & 1);
            const int c = (e < 2) ? r_lo : r_hi;
            const bool valid = (unsigned)(c - 4 * col_abs) < (unsigned)SPAN;
            s[ni][e] = valid ? s[ni][e] * 0.125f : -1e30f;
        }
    }

    // ---- softmax over quad ----
    float mx0 = -1e30f, mx1 = -1e30f;
    #pragma unroll
    for (int ni = 0; ni < 4; ni++) {
        mx0 = fmaxf(mx0, fmaxf(s[ni][0], s[ni][1]));
        mx1 = fmaxf(mx1, fmaxf(s[ni][2], s[ni][3]));
    }
    mx0 = fmaxf(mx0, __shfl_xor_sync(0xffffffffu, mx0, 1));
    mx0 = fmaxf(mx0, __shfl_xor_sync(0xffffffffu, mx0, 2));
    mx1 = fmaxf(mx1, __shfl_xor_sync(0xffffffffu, mx1, 1));
    mx1 = fmaxf(mx1, __shfl_xor_sync(0xffffffffu, mx1, 2));
    float sum0 = 0.0f, sum1 = 0.0f;
    #pragma unroll
    for (int ni = 0; ni < 4; ni++) {
        s[ni][0] = __expf(s[ni][0] - mx0); sum0 += s[ni][0];
        s[ni][1] = __expf(s[ni][1] - mx0); sum0 += s[ni][1];
        s[ni][2] = __expf(s[ni][2] - mx1); sum1 += s[ni][2];
        s[ni][3] = __expf(s[ni][3] - mx1); sum1 += s[ni][3];
    }
    sum0 += __shfl_xor_sync(0xffffffffu, sum0, 1);
    sum0 += __shfl_xor_sync(0xffffffffu, sum0, 2);
    sum1 += __shfl_xor_sync(0xffffffffu, sum1, 1);
    sum1 += __shfl_xor_sync(0xffffffffu, sum1, 2);
    const float inv0 = 1.0f / sum0, inv1 = 1.0f / sum1;
    #pragma unroll
    for (int ni = 0; ni < 4; ni++) {
        s[ni][0] *= inv0; s[ni][1] *= inv0;
        s[ni][2] *= inv1; s[ni][3] *= inv1;
    }

    // ---- pack P frags (hi + lo) ----
    uint32_t aPh[2][4], aPl[2][4];
    #pragma unroll
    for (int kc = 0; kc < 2; kc++) {
        #pragma unroll
        for (int half = 0; half < 2; half++) {
            const float* p = s[2 * kc + half];
            float lo0 = p[0] - __bfloat162float(__float2bfloat16_rn(p[0]));
            float lo1 = p[1] - __bfloat162float(__float2bfloat16_rn(p[1]));
            float lo2 = p[2] - __bfloat162float(__float2bfloat16_rn(p[2]));
            float lo3 = p[3] - __bfloat162float(__float2bfloat16_rn(p[3]));
            aPh[kc][half * 2 + 0] = pack_bf2(p[0], p[1]);
            aPh[kc][half * 2 + 1] = pack_bf2(p[2], p[3]);
            aPl[kc][half * 2 + 0] = pack_bf2(lo0, lo1);
            aPl[kc][half * 2 + 1] = pack_bf2(lo2, lo3);
        }
    }

    // ---- O = P @ V (V row-major, B-frags via ldmatrix.trans) ----
    float o[8][4];
    #pragma unroll
    for (int ni = 0; ni < 8; ni++)
        #pragma unroll
        for (int e = 0; e < 4; e++) o[ni][e] = 0.0f;
    const uint32_t vrow = (uint32_t)((lane & 7) + ((lane >> 3) & 1) * 8) * AROWB;
    #pragma unroll
    for (int kc = 0; kc < 2; kc++) {
        const uint32_t kro = (uint32_t)(kc * 16) * AROWB;
        #pragma unroll
        for (int ni = 0; ni < 8; ni++) {
            uint32_t b2[2];
            const uint32_t bo = kro + vrow + (uint32_t)(ni * 16);
            ldsm_x2_trans(b2, sb + SVH + bo);
            mma_bf16(o[ni], aPh[kc], b2);
            mma_bf16(o[ni], aPl[kc], b2);
            ldsm_x2_trans(b2, sb + SVL + bo);
            mma_bf16(o[ni], aPh[kc], b2);
        }
    }

    // ---- store ctx hi/lo ----
    #pragma unroll
    for (int ni = 0; ni < 8; ni++) {
        const int col = ni * 8 + (lane & 3) * 2;
        const size_t i0 = (size_t)(b * LQ + r_lo) * DMODEL + h * DHEAD + col;
        const size_t i1 = (size_t)(b * LQ + r_hi) * DMODEL + h * DHEAD + col;
        __nv_bfloat16 h0, h1, h2, h3, l0, l1, l2, l3;
        bf16_split(o[ni][0], h0, l0); bf16_split(o[ni][1], h1, l1);
        bf16_split(o[ni][2], h2, l2); bf16_split(o[ni][3], h3, l3);
        *(__nv_bfloat162*)&ctxh[i0] = __nv_bfloat162(h0, h1);
        *(__nv_bfloat162*)&ctxl[i0] = __nv_bfloat162(l0, l1);
        *(__nv_bfloat162*)&ctxh[i1] = __nv_bfloat162(h2, h3);
        *(__nv_bfloat162*)&ctxl[i1] = __nv_bfloat162(l2, l3);
    }
}

// ---------------- launch ----------------
extern "C" void kernel_launch(void* const* d_in, const int* in_sizes, int n_in,
                              void* d_out, int out_size)
{
    const float* q    = (const float*)d_in[0];
    const float* k    = (const float*)d_in[1];
    const float* v    = (const float*)d_in[2];
    const float* Wq   = (const float*)d_in[3];
    const float* Wk   = (const float*)d_in[4];
    const float* Wv   = (const float*)d_in[5];
    const float* Wout = (const float*)d_in[6];
    float* out = (float*)d_out;

    __nv_bfloat16 *qh, *ql, *kh, *kl, *vh, *vl;
    __nv_bfloat16 *Qph, *Qpl, *Kph, *Kpl, *Vph, *Vpl, *ch, *cl, *Wth, *Wtl;
    cudaGetSymbolAddress((void**)&qh,  g_qh);  cudaGetSymbolAddress((void**)&ql,  g_ql);
    cudaGetSymbolAddress((void**)&kh,  g_kh);  cudaGetSymbolAddress((void**)&kl,  g_kl);
    cudaGetSymbolAddress((void**)&vh,  g_vh);  cudaGetSymbolAddress((void**)&vl,  g_vl);
    cudaGetSymbolAddress((void**)&Qph, g_Qph); cudaGetSymbolAddress((void**)&Qpl, g_Qpl);
    cudaGetSymbolAddress((void**)&Kph, g_Kph); cudaGetSymbolAddress((void**)&Kpl, g_Kpl);
    cudaGetSymbolAddress((void**)&Vph, g_Vph); cudaGetSymbolAddress((void**)&Vpl, g_Vpl);
    cudaGetSymbolAddress((void**)&ch,  g_ch);  cudaGetSymbolAddress((void**)&cl,  g_cl);
    cudaGetSymbolAddress((void**)&Wth, g_Wth); cudaGetSymbolAddress((void**)&Wtl, g_Wtl);

    cudaFuncSetAttribute(proj_fused_kernel,
                         cudaFuncAttributeMaxDynamicSharedMemorySize, GEMM_SMEM);
    cudaFuncSetAttribute(outproj_kernel,
                         cudaFuncAttributeMaxDynamicSharedMemorySize, GEMM_SMEM);

    const int totalV = (MQ * DMODEL + 2 * MK * DMODEL) / 4;
    split_act_kernel<<<(totalV + 255) / 256, 256>>>(q, k, v, qh, ql, kh, kl, vh, vl);
    split_w_kernel<<<dim3(16, 16, 4), dim3(32, 32)>>>(Wq, Wk, Wv, Wout, Wth, Wtl);
    proj_fused_kernel<<<384, 256, GEMM_SMEM>>>(qh, ql, kh, kl, vh, vl, Wth, Wtl,
                                               Qph, Qpl, Kph, Kpl, Vph, Vpl);
    attn_tc_kernel<<<dim3(LQ / 64, HEADS, B_SZ), 128>>>(Qph, Qpl, Kph, Kpl, Vph, Vpl, ch, cl);
    outproj_kernel<<<dim3(4, 64), 256, GEMM_SMEM>>>(ch, cl, Wth, Wtl, out);
}

// round 7
// speedup vs baseline: 1.3570x; 1.0769x over previous
#include <cuda_runtime.h>
#include <cuda_bf16.h>
#include <cstdint>

#define B_SZ   2
#define LQ     4096
#define LKV    1024
#define DMODEL 512
#define HEADS  8
#define DHEAD  64
#define SPAN   64
#define STRIDE 4

#define MQ (B_SZ * LQ)    // 8192
#define MK (B_SZ * LKV)   // 2048

// ---------------- scratch ----------------
__device__ __nv_bfloat16 g_Qph[MQ * DMODEL], g_Qpl[MQ * DMODEL];
__device__ __nv_bfloat16 g_Kph[MK * DMODEL], g_Kpl[MK * DMODEL];
__device__ __nv_bfloat16 g_Vph[MK * DMODEL], g_Vpl[MK * DMODEL];
__device__ __nv_bfloat16 g_ch[MQ * DMODEL], g_cl[MQ * DMODEL];
__device__ __nv_bfloat16 g_Wth[4 * DMODEL * DMODEL], g_Wtl[4 * DMODEL * DMODEL];

// ---------------- helpers ----------------
__device__ __forceinline__ uint32_t smem_u32(const void* p) {
    uint32_t a;
    asm("{ .reg .u64 t; cvta.to.shared.u64 t, %1; cvt.u32.u64 %0, t; }" : "=r"(a) : "l"(p));
    return a;
}
__device__ __forceinline__ void bf16_split(float x, __nv_bfloat16& h, __nv_bfloat16& l) {
    h = __float2bfloat16_rn(x);
    l = __float2bfloat16_rn(x - __bfloat162float(h));
}
__device__ __forceinline__ uint32_t pack_bf2(float a, float b) {
    __nv_bfloat162 t(__float2bfloat16_rn(a), __float2bfloat16_rn(b));
    return *(uint32_t*)&t;
}
__device__ __forceinline__ void ldsm_x4(uint32_t* r, uint32_t a) {
    asm volatile("ldmatrix.sync.aligned.m8n8.x4.shared.b16 {%0,%1,%2,%3}, [%4];"
        : "=r"(r[0]), "=r"(r[1]), "=r"(r[2]), "=r"(r[3]) : "r"(a));
}
__device__ __forceinline__ void ldsm_x2(uint32_t* r, uint32_t a) {
    asm volatile("ldmatrix.sync.aligned.m8n8.x2.shared.b16 {%0,%1}, [%2];"
        : "=r"(r[0]), "=r"(r[1]) : "r"(a));
}
__device__ __forceinline__ void ldsm_x2_trans(uint32_t* r, uint32_t a) {
    asm volatile("ldmatrix.sync.aligned.m8n8.x2.trans.shared.b16 {%0,%1}, [%2];"
        : "=r"(r[0]), "=r"(r[1]) : "r"(a));
}
__device__ __forceinline__ void mma_bf16(float* c, const uint32_t* a, const uint32_t* b) {
    asm volatile(
        "mma.sync.aligned.m16n8k16.row.col.f32.bf16.bf16.f32 "
        "{%0,%1,%2,%3}, {%4,%5,%6,%7}, {%8,%9}, {%0,%1,%2,%3};"
        : "+f"(c[0]), "+f"(c[1]), "+f"(c[2]), "+f"(c[3])
        : "r"(a[0]), "r"(a[1]), "r"(a[2]), "r"(a[3]), "r"(b[0]), "r"(b[1]));
}
__device__ __forceinline__ void cp16(uint32_t dst, const void* src) {
    asm volatile("cp.async.cg.shared.global [%0], [%1], 16;" :: "r"(dst), "l"(src));
}
#define CP_COMMIT() asm volatile("cp.async.commit_group;" ::: "memory")
#define CP_WAIT0()  asm volatile("cp.async.wait_group 0;" ::: "memory")

// ---------------- prepass: transpose + split weights ----------------
__global__ __launch_bounds__(1024) void split_w_kernel(
    const float* __restrict__ W0, const float* __restrict__ W1,
    const float* __restrict__ W2, const float* __restrict__ W3,
    __nv_bfloat16* __restrict__ Wth, __nv_bfloat16* __restrict__ Wtl)
{
    __shared__ float t[32][33];
    const int z = blockIdx.z;
    const float* W = (z == 0) ? W0 : (z == 1) ? W1 : (z == 2) ? W2 : W3;
    const int n0 = blockIdx.x * 32, k0 = blockIdx.y * 32;
    const int tx = threadIdx.x, ty = threadIdx.y;
    t[ty][tx] = W[(size_t)(k0 + ty) * DMODEL + n0 + tx];
    __syncthreads();
    float x = t[tx][ty];
    __nv_bfloat16 h, l;
    bf16_split(x, h, l);
    size_t o = (size_t)z * DMODEL * DMODEL + (size_t)(n0 + ty) * DMODEL + k0 + tx;
    Wth[o] = h; Wtl[o] = l;
}

// ---------------- cp.async double-buffered bf16x3 GEMM ----------------
// C[128,128] = A[128,512] @ Bt[128,512]^T ; K-chunk 32, 80B rows, 2 stages.
// AFP32: A is fp32 in gmem; split to bf16 hi/lo in-register at stage fill.
#define GROWB 80
#define GTSZ  (128 * GROWB)        // 10240
#define STG   (4 * GTSZ)           // 40960 bytes per stage
#define GEMM_SMEM (2 * STG)        // 81920
#define NCH   16                   // 512 / 32

template<bool AFP32, bool SPLITOUT>
__device__ __forceinline__ void gemm_pipe_tile(
    const float* __restrict__ A32,
    const __nv_bfloat16* __restrict__ Ah, const __nv_bfloat16* __restrict__ Al,
    const __nv_bfloat16* __restrict__ Bh, const __nv_bfloat16* __restrict__ Bl,
    float* __restrict__ Cf, __nv_bfloat16* __restrict__ Ch, __nv_bfloat16* __restrict__ Cl,
    int row0, int col0)
{
    extern __shared__ char sm[];
    const uint32_t sb = smem_u32(sm);
    const int tid  = threadIdx.x;
    const int wid  = tid >> 5;
    const int lane = tid & 31;
    const int m0 = (wid & 1) * 64;
    const int n0 = (wid >> 1) * 32;

    float acc[4][4][4];
    #pragma unroll
    for (int mi = 0; mi < 4; mi++)
        #pragma unroll
        for (int ni = 0; ni < 4; ni++)
            #pragma unroll
            for (int e = 0; e < 4; e++) acc[mi][ni][e] = 0.0f;

    const uint32_t a_off = (uint32_t)(m0 + (lane & 15)) * GROWB + ((lane >> 4) << 4);
    const uint32_t b_off = (uint32_t)((lane & 7) + ((lane >> 4) & 1) * 8) * GROWB
                         + (((lane >> 3) & 1) << 4);

    // stage coords: 2 positions per thread (row, 16B-bf16 segment)
    const int ir0 = (tid + 0)   >> 2, ic0 = ((tid + 0)   & 3) << 4;
    const int ir1 = (tid + 256) >> 2, ic1 = ((tid + 256) & 3) << 4;

    float ar[2][8];                 // A fp32 prefetch regs (AFP32 path)

    auto ldA_regs = [&](int ch) {
        if (!AFP32) return;
        const int kc = ch * 32;
        {
            const float* pa = A32 + (size_t)(row0 + ir0) * DMODEL + kc + (ic0 >> 1);
            float4 x = *(const float4*)pa, y = *(const float4*)(pa + 4);
            ar[0][0]=x.x; ar[0][1]=x.y; ar[0][2]=x.z; ar[0][3]=x.w;
            ar[0][4]=y.x; ar[0][5]=y.y; ar[0][6]=y.z; ar[0][7]=y.w;
        }
        {
            const float* pa = A32 + (size_t)(row0 + ir1) * DMODEL + kc + (ic1 >> 1);
            float4 x = *(const float4*)pa, y = *(const float4*)(pa + 4);
            ar[1][0]=x.x; ar[1][1]=x.y; ar[1][2]=x.z; ar[1][3]=x.w;
            ar[1][4]=y.x; ar[1][5]=y.y; ar[1][6]=y.z; ar[1][7]=y.w;
        }
    };
    auto stsA = [&](int buf) {
        if (!AFP32) return;
        #pragma unroll
        for (int p = 0; p < 2; p++) {
            const int ir = p ? ir1 : ir0;
            const int ic = p ? ic1 : ic0;
            const float* a = ar[p];
            uint4 hi, lo;
            hi.x = pack_bf2(a[0], a[1]); hi.y = pack_bf2(a[2], a[3]);
            hi.z = pack_bf2(a[4], a[5]); hi.w = pack_bf2(a[6], a[7]);
            float l0 = a[0] - __bfloat162float(__float2bfloat16_rn(a[0]));
            float l1 = a[1] - __bfloat162float(__float2bfloat16_rn(a[1]));
            float l2 = a[2] - __bfloat162float(__float2bfloat16_rn(a[2]));
            float l3 = a[3] - __bfloat162float(__float2bfloat16_rn(a[3]));
            float l4 = a[4] - __bfloat162float(__float2bfloat16_rn(a[4]));
            float l5 = a[5] - __bfloat162float(__float2bfloat16_rn(a[5]));
            float l6 = a[6] - __bfloat162float(__float2bfloat16_rn(a[6]));
            float l7 = a[7] - __bfloat162float(__float2bfloat16_rn(a[7]));
            lo.x = pack_bf2(l0, l1); lo.y = pack_bf2(l2, l3);
            lo.z = pack_bf2(l4, l5); lo.w = pack_bf2(l6, l7);
            const uint32_t dso = (uint32_t)ir * GROWB + ic + (uint32_t)buf * STG;
            *(uint4*)(sm + 0 * GTSZ + dso) = hi;
            *(uint4*)(sm + 1 * GTSZ + dso) = lo;
        }
    };
    auto issue_cp = [&](int ch, int buf) {
        const uint32_t stg = sb + (uint32_t)buf * STG;
        const size_t kb = (size_t)ch * 64;
        #pragma unroll
        for (int p = 0; p < 2; p++) {
            const int ir = p ? ir1 : ir0;
            const int ic = p ? ic1 : ic0;
            const uint32_t dso = (uint32_t)ir * GROWB + ic;
            const size_t gb = (size_t)(col0 + ir) * (DMODEL * 2) + kb + ic;
            cp16(stg + 2 * GTSZ + dso, (const char*)Bh + gb);
            cp16(stg + 3 * GTSZ + dso, (const char*)Bl + gb);
            if (!AFP32) {
                const size_t ga = (size_t)(row0 + ir) * (DMODEL * 2) + kb + ic;
                cp16(stg + 0 * GTSZ + dso, (const char*)Ah + ga);
                cp16(stg + 1 * GTSZ + dso, (const char*)Al + ga);
            }
        }
        CP_COMMIT();
    };

    ldA_regs(0);
    issue_cp(0, 0);

    for (int ch = 0; ch < NCH; ch++) {
        CP_WAIT0();
        __syncthreads();                   // buf ch&1 free for A STS; B for ch arrived
        stsA(ch & 1);                      // A hi/lo for chunk ch (from regs)
        if (ch + 1 < NCH) { issue_cp(ch + 1, (ch + 1) & 1); ldA_regs(ch + 1); }
        __syncthreads();                   // A STS visible

        const uint32_t stg = sb + (uint32_t)(ch & 1) * STG;
        const uint32_t aH = stg + 0 * GTSZ + a_off;
        const uint32_t aL = stg + 1 * GTSZ + a_off;
        const uint32_t bH = stg + 2 * GTSZ + b_off + (uint32_t)n0 * GROWB;
        const uint32_t bL = stg + 3 * GTSZ + b_off + (uint32_t)n0 * GROWB;

        #pragma unroll
        for (int ks = 0; ks < 2; ks++) {
            const uint32_t ko = (uint32_t)ks * 32;
            uint32_t af[4][4];
            // ---- phase 1: A-hi (Ah*Bh + Ah*Bl) ----
            #pragma unroll
            for (int mi = 0; mi < 4; mi++)
                ldsm_x4(af[mi], aH + (uint32_t)(mi * 16) * GROWB + ko);
            #pragma unroll
            for (int nj = 0; nj < 2; nj++) {
                uint32_t bh4[4], bl4[4];
                const uint32_t bno = (uint32_t)(nj * 16) * GROWB + ko;
                ldsm_x4(bh4, bH + bno);
                ldsm_x4(bl4, bL + bno);
                #pragma unroll
                for (int mi = 0; mi < 4; mi++) {
                    mma_bf16(acc[mi][2 * nj + 0], af[mi], bh4 + 0);
                    mma_bf16(acc[mi][2 * nj + 0], af[mi], bl4 + 0);
                    mma_bf16(acc[mi][2 * nj + 1], af[mi], bh4 + 2);
                    mma_bf16(acc[mi][2 * nj + 1], af[mi], bl4 + 2);
                }
            }
            // ---- phase 2: A-lo (Al*Bh), reuse af regs ----
            #pragma unroll
            for (int mi = 0; mi < 4; mi++)
                ldsm_x4(af[mi], aL + (uint32_t)(mi * 16) * GROWB + ko);
            #pragma unroll
            for (int nj = 0; nj < 2; nj++) {
                uint32_t bh4[4];
                ldsm_x4(bh4, bH + (uint32_t)(nj * 16) * GROWB + ko);
                #pragma unroll
                for (int mi = 0; mi < 4; mi++) {
                    mma_bf16(acc[mi][2 * nj + 0], af[mi], bh4 + 0);
                    mma_bf16(acc[mi][2 * nj + 1], af[mi], bh4 + 2);
                }
            }
        }
    }

    // epilogue
    #pragma unroll
    for (int mi = 0; mi < 4; mi++) {
        #pragma unroll
        for (int ni = 0; ni < 4; ni++) {
            const int row = row0 + m0 + mi * 16 + (lane >> 2);
            const int col = col0 + n0 + ni * 8 + (lane & 3) * 2;
            const float* a = acc[mi][ni];
            if (SPLITOUT) {
                __nv_bfloat16 h0, h1, h2, h3, l0, l1, l2, l3;
                bf16_split(a[0], h0, l0); bf16_split(a[1], h1, l1);
                bf16_split(a[2], h2, l2); bf16_split(a[3], h3, l3);
                *(__nv_bfloat162*)&Ch[(size_t)row * DMODEL + col] = __nv_bfloat162(h0, h1);
                *(__nv_bfloat162*)&Cl[(size_t)row * DMODEL + col] = __nv_bfloat162(l0, l1);
                *(__nv_bfloat162*)&Ch[(size_t)(row + 8) * DMODEL + col] = __nv_bfloat162(h2, h3);
                *(__nv_bfloat162*)&Cl[(size_t)(row + 8) * DMODEL + col] = __nv_bfloat162(l2, l3);
            } else {
                *(float2*)&Cf[(size_t)row * DMODEL + col] = make_float2(a[0], a[1]);
                *(float2*)&Cf[(size_t)(row + 8) * DMODEL + col] = make_float2(a[2], a[3]);
            }
        }
    }
}

__global__ __launch_bounds__(256, 2) void proj_fused_kernel(
    const float* __restrict__ q, const float* __restrict__ k, const float* __restrict__ v,
    const __nv_bfloat16* __restrict__ Wth, const __nv_bfloat16* __restrict__ Wtl,
    __nv_bfloat16* __restrict__ Qph, __nv_bfloat16* __restrict__ Qpl,
    __nv_bfloat16* __restrict__ Kph, __nv_bfloat16* __restrict__ Kpl,
    __nv_bfloat16* __restrict__ Vph, __nv_bfloat16* __restrict__ Vpl)
{
    const int bid = blockIdx.x;
    const size_t WSZ = (size_t)DMODEL * DMODEL;
    const float* A; const __nv_bfloat16 *Bh, *Bl; __nv_bfloat16 *Ch, *Cl; int t;
    if (bid < 256)      { A = q; Bh = Wth;           Bl = Wtl;           Ch = Qph; Cl = Qpl; t = bid; }
    else if (bid < 320) { A = k; Bh = Wth + WSZ;     Bl = Wtl + WSZ;     Ch = Kph; Cl = Kpl; t = bid - 256; }
    else                { A = v; Bh = Wth + 2 * WSZ; Bl = Wtl + 2 * WSZ; Ch = Vph; Cl = Vpl; t = bid - 320; }
    gemm_pipe_tile<true, true>(A, nullptr, nullptr, Bh, Bl, nullptr, Ch, Cl,
                               (t >> 2) * 128, (t & 3) * 128);
}

__global__ __launch_bounds__(256, 2) void outproj_kernel(
    const __nv_bfloat16* __restrict__ ch, const __nv_bfloat16* __restrict__ cl,
    const __nv_bfloat16* __restrict__ Wth, const __nv_bfloat16* __restrict__ Wtl,
    float* __restrict__ out)
{
    const size_t WSZ = (size_t)DMODEL * DMODEL;
    gemm_pipe_tile<false, false>(nullptr, ch, cl, Wth + 3 * WSZ, Wtl + 3 * WSZ,
                                 out, nullptr, nullptr,
                                 blockIdx.y * 128, blockIdx.x * 128);
}

// ---------------- tensor-core sparse attention (unchanged from R6) ----------------
#define AROWB 144
#define SQH 0
#define SQL (SQH + 64 * AROWB)
#define SKH (SQL + 64 * AROWB)
#define SKL (SKH + 32 * AROWB)
#define SVH (SKL + 32 * AROWB)
#define SVL (SVH + 32 * AROWB)
#define ATT_SM (SVL + 32 * AROWB)

__global__ __launch_bounds__(128) void attn_tc_kernel(
    const __nv_bfloat16* __restrict__ Qph, const __nv_bfloat16* __restrict__ Qpl,
    const __nv_bfloat16* __restrict__ Kph, const __nv_bfloat16* __restrict__ Kpl,
    const __nv_bfloat16* __restrict__ Vph, const __nv_bfloat16* __restrict__ Vpl,
    __nv_bfloat16* __restrict__ ctxh, __nv_bfloat16* __restrict__ ctxl)
{
    __shared__ char sm[ATT_SM];
    const uint32_t sb = smem_u32(sm);
    const int c0  = blockIdx.x * 64;
    const int h   = blockIdx.y;
    const int b   = blockIdx.z;
    const int tid = threadIdx.x;
    const int wid = tid >> 5;
    const int lane = tid & 31;

    int jmin = (c0 - (SPAN - 1) + (STRIDE - 1)) >> 2;
    if (jmin < 0) jmin = 0;
    int jmax = (c0 + 63) >> 2;
    if (jmax > LKV - 1) jmax = LKV - 1;
    const int nrows = jmax - jmin + 1;

    for (int u = tid; u < (32 - nrows) * 36; u += 128) {
        const int r = nrows + u / 36, w = u % 36;
        ((uint32_t*)(sm + SVH))[r * 36 + w] = 0;
        ((uint32_t*)(sm + SVL))[r * 36 + w] = 0;
    }
    for (int u = tid; u < 512; u += 128) {
        const int r = u >> 3, cb = (u & 7) << 4;
        const size_t gb = (size_t)(b * LQ + c0 + r) * (DMODEL * 2) + h * DHEAD * 2 + cb;
        *(uint4*)(sm + SQH + r * AROWB + cb) = *(const uint4*)((const char*)Qph + gb);
        *(uint4*)(sm + SQL + r * AROWB + cb) = *(const uint4*)((const char*)Qpl + gb);
    }
    for (int u = tid; u < nrows * 8; u += 128) {
        const int r = u >> 3, cb = (u & 7) << 4;
        const size_t gb = (size_t)(b * LKV + jmin + r) * (DMODEL * 2) + h * DHEAD * 2 + cb;
        *(uint4*)(sm + SKH + r * AROWB + cb) = *(const uint4*)((const char*)Kph + gb);
        *(uint4*)(sm + SKL + r * AROWB + cb) = *(const uint4*)((const char*)Kpl + gb);
        *(uint4*)(sm + SVH + r * AROWB + cb) = *(const uint4*)((const char*)Vph + gb);
        *(uint4*)(sm + SVL + r * AROWB + cb) = *(const uint4*)((const char*)Vpl + gb);
    }
    __syncthreads();

    float s[4][4];
    #pragma unroll
    for (int ni = 0; ni < 4; ni++)
        #pragma unroll
        for (int e = 0; e < 4; e++) s[ni][e] = 0.0f;

    const uint32_t qa = sb + (uint32_t)(wid * 16 + (lane & 15)) * AROWB + ((lane >> 4) << 4);
    const uint32_t kb = sb + SKH + (uint32_t)(lane & 7) * AROWB + (((lane >> 3) & 1) << 4);
    #pragma unroll
    for (int ks = 0; ks < 4; ks++) {
        const uint32_t ko = (uint32_t)ks * 32;
        uint32_t qh4[4], ql4[4], b2[2];
        ldsm_x4(qh4, qa + SQH + ko);
        ldsm_x4(ql4, qa + SQL + ko);
        #pragma unroll
        for (int ni = 0; ni < 4; ni++) {
            const uint32_t bo = kb + (uint32_t)(ni * 8) * AROWB + ko;
            ldsm_x2(b2, bo);
            mma_bf16(s[ni], qh4, b2);
            mma_bf16(s[ni], ql4, b2);
            ldsm_x2(b2, bo + (SKL - SKH));
            mma_bf16(s[ni], qh4, b2);
        }
    }

    const int r_lo = c0 + wid * 16 + (lane >> 2);
    const int r_hi = r_lo + 8;
    #pragma unroll
    for (int ni = 0; ni < 4; ni++) {
        #pragma unroll
        for (int e = 0; e < 4; e++) {
            const int col_abs = jmin + ni * 8 + (lane & 3) * 2 + (e & 1);
            const int c = (e < 2) ? r_lo : r_hi;
            const bool valid = (unsigned)(c - 4 * col_abs) < (unsigned)SPAN;
            s[ni][e] = valid ? s[ni][e] * 0.125f : -1e30f;
        }
    }

    float mx0 = -1e30f, mx1 = -1e30f;
    #pragma unroll
    for (int ni = 0; ni < 4; ni++) {
        mx0 = fmaxf(mx0, fmaxf(s[ni][0], s[ni][1]));
        mx1 = fmaxf(mx1, fmaxf(s[ni][2], s[ni][3]));
    }
    mx0 = fmaxf(mx0, __shfl_xor_sync(0xffffffffu, mx0, 1));
    mx0 = fmaxf(mx0, __shfl_xor_sync(0xffffffffu, mx0, 2));
    mx1 = fmaxf(mx1, __shfl_xor_sync(0xffffffffu, mx1, 1));
    mx1 = fmaxf(mx1, __shfl_xor_sync(0xffffffffu, mx1, 2));
    float sum0 = 0.0f, sum1 = 0.0f;
    #pragma unroll
    for (int ni = 0; ni < 4; ni++) {
        s[ni][0] = __expf(s[ni][0] - mx0); sum0 += s[ni][0];
        s[ni][1] = __expf(s[ni][1] - mx0); sum0 += s[ni][1];
        s[ni][2] = __expf(s[ni][2] - mx1); sum1 += s[ni][2];
        s[ni][3] = __expf(s[ni][3] - mx1); sum1 += s[ni][3];
    }
    sum0 += __shfl_xor_sync(0xffffffffu, sum0, 1);
    sum0 += __shfl_xor_sync(0xffffffffu, sum0, 2);
    sum1 += __shfl_xor_sync(0xffffffffu, sum1, 1);
    sum1 += __shfl_xor_sync(0xffffffffu, sum1, 2);
    const float inv0 = 1.0f / sum0, inv1 = 1.0f / sum1;
    #pragma unroll
    for (int ni = 0; ni < 4; ni++) {
        s[ni][0] *= inv0; s[ni][1] *= inv0;
        s[ni][2] *= inv1; s[ni][3] *= inv1;
    }

    uint32_t aPh[2][4], aPl[2][4];
    #pragma unroll
    for (int kc = 0; kc < 2; kc++) {
        #pragma unroll
        for (int half = 0; half < 2; half++) {
            const float* p = s[2 * kc + half];
            float lo0 = p[0] - __bfloat162float(__float2bfloat16_rn(p[0]));
            float lo1 = p[1] - __bfloat162float(__float2bfloat16_rn(p[1]));
            float lo2 = p[2] - __bfloat162float(__float2bfloat16_rn(p[2]));
            float lo3 = p[3] - __bfloat162float(__float2bfloat16_rn(p[3]));
            aPh[kc][half * 2 + 0] = pack_bf2(p[0], p[1]);
            aPh[kc][half * 2 + 1] = pack_bf2(p[2], p[3]);
            aPl[kc][half * 2 + 0] = pack_bf2(lo0, lo1);
            aPl[kc][half * 2 + 1] = pack_bf2(lo2, lo3);
        }
    }

    float o[8][4];
    #pragma unroll
    for (int ni = 0; ni < 8; ni++)
        #pragma unroll
        for (int e = 0; e < 4; e++) o[ni][e] = 0.0f;
    const uint32_t vrow = (uint32_t)((lane & 7) + ((lane >> 3) & 1) * 8) * AROWB;
    #pragma unroll
    for (int kc = 0; kc < 2; kc++) {
        const uint32_t kro = (uint32_t)(kc * 16) * AROWB;
        #pragma unroll
        for (int ni = 0; ni < 8; ni++) {
            uint32_t b2[2];
            const uint32_t bo = kro + vrow + (uint32_t)(ni * 16);
            ldsm_x2_trans(b2, sb + SVH + bo);
            mma_bf16(o[ni], aPh[kc], b2);
            mma_bf16(o[ni], aPl[kc], b2);
            ldsm_x2_trans(b2, sb + SVL + bo);
            mma_bf16(o[ni], aPh[kc], b2);
        }
    }

    #pragma unroll
    for (int ni = 0; ni < 8; ni++) {
        const int col = ni * 8 + (lane & 3) * 2;
        const size_t i0 = (size_t)(b * LQ + r_lo) * DMODEL + h * DHEAD + col;
        const size_t i1 = (size_t)(b * LQ + r_hi) * DMODEL + h * DHEAD + col;
        __nv_bfloat16 h0, h1, h2, h3, l0, l1, l2, l3;
        bf16_split(o[ni][0], h0, l0); bf16_split(o[ni][1], h1, l1);
        bf16_split(o[ni][2], h2, l2); bf16_split(o[ni][3], h3, l3);
        *(__nv_bfloat162*)&ctxh[i0] = __nv_bfloat162(h0, h1);
        *(__nv_bfloat162*)&ctxl[i0] = __nv_bfloat162(l0, l1);
        *(__nv_bfloat162*)&ctxh[i1] = __nv_bfloat162(h2, h3);
        *(__nv_bfloat162*)&ctxl[i1] = __nv_bfloat162(l2, l3);
    }
}

// ---------------- launch ----------------
extern "C" void kernel_launch(void* const* d_in, const int* in_sizes, int n_in,
                              void* d_out, int out_size)
{
    const float* q    = (const float*)d_in[0];
    const float* k    = (const float*)d_in[1];
    const float* v    = (const float*)d_in[2];
    const float* Wq   = (const float*)d_in[3];
    const float* Wk   = (const float*)d_in[4];
    const float* Wv   = (const float*)d_in[5];
    const float* Wout = (const float*)d_in[6];
    float* out = (float*)d_out;

    __nv_bfloat16 *Qph, *Qpl, *Kph, *Kpl, *Vph, *Vpl, *ch, *cl, *Wth, *Wtl;
    cudaGetSymbolAddress((void**)&Qph, g_Qph); cudaGetSymbolAddress((void**)&Qpl, g_Qpl);
    cudaGetSymbolAddress((void**)&Kph, g_Kph); cudaGetSymbolAddress((void**)&Kpl, g_Kpl);
    cudaGetSymbolAddress((void**)&Vph, g_Vph); cudaGetSymbolAddress((void**)&Vpl, g_Vpl);
    cudaGetSymbolAddress((void**)&ch,  g_ch);  cudaGetSymbolAddress((void**)&cl,  g_cl);
    cudaGetSymbolAddress((void**)&Wth, g_Wth); cudaGetSymbolAddress((void**)&Wtl, g_Wtl);

    cudaFuncSetAttribute(proj_fused_kernel,
                         cudaFuncAttributeMaxDynamicSharedMemorySize, GEMM_SMEM);
    cudaFuncSetAttribute(outproj_kernel,
                         cudaFuncAttributeMaxDynamicSharedMemorySize, GEMM_SMEM);

    split_w_kernel<<<dim3(16, 16, 4), dim3(32, 32)>>>(Wq, Wk, Wv, Wout, Wth, Wtl);
    proj_fused_kernel<<<384, 256, GEMM_SMEM>>>(q, k, v, Wth, Wtl,
                                               Qph, Qpl, Kph, Kpl, Vph, Vpl);
    attn_tc_kernel<<<dim3(LQ / 64, HEADS, B_SZ), 128>>>(Qph, Qpl, Kph, Kpl, Vph, Vpl, ch, cl);
    outproj_kernel<<<dim3(4, 64), 256, GEMM_SMEM>>>(ch, cl, Wth, Wtl, out);
}

// round 8
// speedup vs baseline: 1.7452x; 1.2861x over previous
#include <cuda_runtime.h>
#include <cuda_fp16.h>
#include <cstdint>

#define B_SZ   2
#define LQ     4096
#define LKV    1024
#define DMODEL 512
#define HEADS  8
#define DHEAD  64
#define SPAN   64
#define STRIDE 4

#define MQ (B_SZ * LQ)    // 8192
#define MK (B_SZ * LKV)   // 2048

// ---------------- scratch ----------------
__device__ __half g_Qph[MQ * DMODEL], g_Qpl[MQ * DMODEL];
__device__ __half g_Kph[MK * DMODEL], g_Kpl[MK * DMODEL];
__device__ __half g_Vph[MK * DMODEL], g_Vpl[MK * DMODEL];
__device__ __half g_ch[MQ * DMODEL], g_cl[MQ * DMODEL];
__device__ __half g_Wt[4 * DMODEL * DMODEL];   // transposed single-fp16 weights

// ---------------- helpers ----------------
__device__ __forceinline__ uint32_t smem_u32(const void* p) {
    uint32_t a;
    asm("{ .reg .u64 t; cvta.to.shared.u64 t, %1; cvt.u32.u64 %0, t; }" : "=r"(a) : "l"(p));
    return a;
}
__device__ __forceinline__ void h_split(float x, __half& h, __half& l) {
    h = __float2half_rn(x);
    l = __float2half_rn(x - __half2float(h));
}
__device__ __forceinline__ uint32_t pack_h2(float a, float b) {
    __half2 t(__float2half_rn(a), __float2half_rn(b));
    return *(uint32_t*)&t;
}
__device__ __forceinline__ void ldsm_x4(uint32_t* r, uint32_t a) {
    asm volatile("ldmatrix.sync.aligned.m8n8.x4.shared.b16 {%0,%1,%2,%3}, [%4];"
        : "=r"(r[0]), "=r"(r[1]), "=r"(r[2]), "=r"(r[3]) : "r"(a));
}
__device__ __forceinline__ void ldsm_x2(uint32_t* r, uint32_t a) {
    asm volatile("ldmatrix.sync.aligned.m8n8.x2.shared.b16 {%0,%1}, [%2];"
        : "=r"(r[0]), "=r"(r[1]) : "r"(a));
}
__device__ __forceinline__ void ldsm_x2_trans(uint32_t* r, uint32_t a) {
    asm volatile("ldmatrix.sync.aligned.m8n8.x2.trans.shared.b16 {%0,%1}, [%2];"
        : "=r"(r[0]), "=r"(r[1]) : "r"(a));
}
__device__ __forceinline__ void mma_f16(float* c, const uint32_t* a, const uint32_t* b) {
    asm volatile(
        "mma.sync.aligned.m16n8k16.row.col.f32.f16.f16.f32 "
        "{%0,%1,%2,%3}, {%4,%5,%6,%7}, {%8,%9}, {%0,%1,%2,%3};"
        : "+f"(c[0]), "+f"(c[1]), "+f"(c[2]), "+f"(c[3])
        : "r"(a[0]), "r"(a[1]), "r"(a[2]), "r"(a[3]), "r"(b[0]), "r"(b[1]));
}
__device__ __forceinline__ void cp16(uint32_t dst, const void* src) {
    asm volatile("cp.async.cg.shared.global [%0], [%1], 16;" :: "r"(dst), "l"(src));
}
#define CP_COMMIT() asm volatile("cp.async.commit_group;" ::: "memory")
#define CP_WAIT0()  asm volatile("cp.async.wait_group 0;" ::: "memory")

// ---------------- prepass: transpose weights to single fp16 ----------------
__global__ __launch_bounds__(1024) void split_w_kernel(
    const float* __restrict__ W0, const float* __restrict__ W1,
    const float* __restrict__ W2, const float* __restrict__ W3,
    __half* __restrict__ Wt)
{
    __shared__ float t[32][33];
    const int z = blockIdx.z;
    const float* W = (z == 0) ? W0 : (z == 1) ? W1 : (z == 2) ? W2 : W3;
    const int n0 = blockIdx.x * 32, k0 = blockIdx.y * 32;
    const int tx = threadIdx.x, ty = threadIdx.y;
    t[ty][tx] = W[(size_t)(k0 + ty) * DMODEL + n0 + tx];
    __syncthreads();
    size_t o = (size_t)z * DMODEL * DMODEL + (size_t)(n0 + ty) * DMODEL + k0 + tx;
    Wt[o] = __float2half_rn(t[tx][ty]);
}

// ---------------- cp.async double-buffered 2-term fp16 GEMM ----------------
// C[128,128] = A[128,512] @ Bt[128,512]^T ; A split hi/lo fp16, B single fp16.
#define GROWB 80
#define GTSZ  (128 * GROWB)        // 10240
#define STG   (3 * GTSZ)           // 30720 bytes per stage (Ah | Al | B)
#define GEMM_SMEM (2 * STG)        // 61440
#define NCH   16                   // 512 / 32

template<bool AFP32, bool SPLITOUT>
__device__ __forceinline__ void gemm_pipe_tile(
    const float* __restrict__ A32,
    const __half* __restrict__ Ah, const __half* __restrict__ Al,
    const __half* __restrict__ B,
    float* __restrict__ Cf, __half* __restrict__ Ch, __half* __restrict__ Cl,
    int row0, int col0)
{
    extern __shared__ char sm[];
    const uint32_t sb = smem_u32(sm);
    const int tid  = threadIdx.x;
    const int wid  = tid >> 5;
    const int lane = tid & 31;
    const int m0 = (wid & 1) * 64;
    const int n0 = (wid >> 1) * 32;

    float acc[4][4][4];
    #pragma unroll
    for (int mi = 0; mi < 4; mi++)
        #pragma unroll
        for (int ni = 0; ni < 4; ni++)
            #pragma unroll
            for (int e = 0; e < 4; e++) acc[mi][ni][e] = 0.0f;

    const uint32_t a_off = (uint32_t)(m0 + (lane & 15)) * GROWB + ((lane >> 4) << 4);
    const uint32_t b_off = (uint32_t)((lane & 7) + ((lane >> 4) & 1) * 8) * GROWB
                         + (((lane >> 3) & 1) << 4);

    const int ir0 = (tid + 0)   >> 2, ic0 = ((tid + 0)   & 3) << 4;
    const int ir1 = (tid + 256) >> 2, ic1 = ((tid + 256) & 3) << 4;

    float ar[2][8];

    auto ldA_regs = [&](int ch) {
        if (!AFP32) return;
        const int kc = ch * 32;
        {
            const float* pa = A32 + (size_t)(row0 + ir0) * DMODEL + kc + (ic0 >> 1);
            float4 x = *(const float4*)pa, y = *(const float4*)(pa + 4);
            ar[0][0]=x.x; ar[0][1]=x.y; ar[0][2]=x.z; ar[0][3]=x.w;
            ar[0][4]=y.x; ar[0][5]=y.y; ar[0][6]=y.z; ar[0][7]=y.w;
        }
        {
            const float* pa = A32 + (size_t)(row0 + ir1) * DMODEL + kc + (ic1 >> 1);
            float4 x = *(const float4*)pa, y = *(const float4*)(pa + 4);
            ar[1][0]=x.x; ar[1][1]=x.y; ar[1][2]=x.z; ar[1][3]=x.w;
            ar[1][4]=y.x; ar[1][5]=y.y; ar[1][6]=y.z; ar[1][7]=y.w;
        }
    };
    auto stsA = [&](int buf) {
        if (!AFP32) return;
        #pragma unroll
        for (int p = 0; p < 2; p++) {
            const int ir = p ? ir1 : ir0;
            const int ic = p ? ic1 : ic0;
            const float* a = ar[p];
            uint4 hi, lo;
            hi.x = pack_h2(a[0], a[1]); hi.y = pack_h2(a[2], a[3]);
            hi.z = pack_h2(a[4], a[5]); hi.w = pack_h2(a[6], a[7]);
            float l0 = a[0] - __half2float(__float2half_rn(a[0]));
            float l1 = a[1] - __half2float(__float2half_rn(a[1]));
            float l2 = a[2] - __half2float(__float2half_rn(a[2]));
            float l3 = a[3] - __half2float(__float2half_rn(a[3]));
            float l4 = a[4] - __half2float(__float2half_rn(a[4]));
            float l5 = a[5] - __half2float(__float2half_rn(a[5]));
            float l6 = a[6] - __half2float(__float2half_rn(a[6]));
            float l7 = a[7] - __half2float(__float2half_rn(a[7]));
            lo.x = pack_h2(l0, l1); lo.y = pack_h2(l2, l3);
            lo.z = pack_h2(l4, l5); lo.w = pack_h2(l6, l7);
            const uint32_t dso = (uint32_t)ir * GROWB + ic + (uint32_t)buf * STG;
            *(uint4*)(sm + 0 * GTSZ + dso) = hi;
            *(uint4*)(sm + 1 * GTSZ + dso) = lo;
        }
    };
    auto issue_cp = [&](int ch, int buf) {
        const uint32_t stg = sb + (uint32_t)buf * STG;
        const size_t kb = (size_t)ch * 64;
        #pragma unroll
        for (int p = 0; p < 2; p++) {
            const int ir = p ? ir1 : ir0;
            const int ic = p ? ic1 : ic0;
            const uint32_t dso = (uint32_t)ir * GROWB + ic;
            const size_t gb = (size_t)(col0 + ir) * (DMODEL * 2) + kb + ic;
            cp16(stg + 2 * GTSZ + dso, (const char*)B + gb);
            if (!AFP32) {
                const size_t ga = (size_t)(row0 + ir) * (DMODEL * 2) + kb + ic;
                cp16(stg + 0 * GTSZ + dso, (const char*)Ah + ga);
                cp16(stg + 1 * GTSZ + dso, (const char*)Al + ga);
            }
        }
        CP_COMMIT();
    };

    ldA_regs(0);
    issue_cp(0, 0);

    for (int ch = 0; ch < NCH; ch++) {
        CP_WAIT0();
        __syncthreads();
        stsA(ch & 1);
        if (ch + 1 < NCH) { issue_cp(ch + 1, (ch + 1) & 1); ldA_regs(ch + 1); }
        if (AFP32) __syncthreads();          // A STS visibility (cp-only path needs no 2nd bar)

        const uint32_t stg = sb + (uint32_t)(ch & 1) * STG;
        const uint32_t aH = stg + 0 * GTSZ + a_off;
        const uint32_t aL = stg + 1 * GTSZ + a_off;
        const uint32_t bB = stg + 2 * GTSZ + b_off + (uint32_t)n0 * GROWB;

        #pragma unroll
        for (int ks = 0; ks < 2; ks++) {
            const uint32_t ko = (uint32_t)ks * 32;
            uint32_t bf[2][4], af[4][4];
            ldsm_x4(bf[0], bB + ko);
            ldsm_x4(bf[1], bB + (uint32_t)(16 * GROWB) + ko);
            // A-hi term
            #pragma unroll
            for (int mi = 0; mi < 4; mi++)
                ldsm_x4(af[mi], aH + (uint32_t)(mi * 16) * GROWB + ko);
            #pragma unroll
            for (int nj = 0; nj < 2; nj++)
                #pragma unroll
                for (int mi = 0; mi < 4; mi++) {
                    mma_f16(acc[mi][2 * nj + 0], af[mi], bf[nj] + 0);
                    mma_f16(acc[mi][2 * nj + 1], af[mi], bf[nj] + 2);
                }
            // A-lo term (reuse af regs)
            #pragma unroll
            for (int mi = 0; mi < 4; mi++)
                ldsm_x4(af[mi], aL + (uint32_t)(mi * 16) * GROWB + ko);
            #pragma unroll
            for (int nj = 0; nj < 2; nj++)
                #pragma unroll
                for (int mi = 0; mi < 4; mi++) {
                    mma_f16(acc[mi][2 * nj + 0], af[mi], bf[nj] + 0);
                    mma_f16(acc[mi][2 * nj + 1], af[mi], bf[nj] + 2);
                }
        }
        if (!AFP32) __syncthreads();         // keep buffer stable until all warps done
    }

    #pragma unroll
    for (int mi = 0; mi < 4; mi++) {
        #pragma unroll
        for (int ni = 0; ni < 4; ni++) {
            const int row = row0 + m0 + mi * 16 + (lane >> 2);
            const int col = col0 + n0 + ni * 8 + (lane & 3) * 2;
            const float* a = acc[mi][ni];
            if (SPLITOUT) {
                __half h0, h1, h2, h3, l0, l1, l2, l3;
                h_split(a[0], h0, l0); h_split(a[1], h1, l1);
                h_split(a[2], h2, l2); h_split(a[3], h3, l3);
                *(__half2*)&Ch[(size_t)row * DMODEL + col] = __half2(h0, h1);
                *(__half2*)&Cl[(size_t)row * DMODEL + col] = __half2(l0, l1);
                *(__half2*)&Ch[(size_t)(row + 8) * DMODEL + col] = __half2(h2, h3);
                *(__half2*)&Cl[(size_t)(row + 8) * DMODEL + col] = __half2(l2, l3);
            } else {
                *(float2*)&Cf[(size_t)row * DMODEL + col] = make_float2(a[0], a[1]);
                *(float2*)&Cf[(size_t)(row + 8) * DMODEL + col] = make_float2(a[2], a[3]);
            }
        }
    }
}

__global__ __launch_bounds__(256, 2) void proj_fused_kernel(
    const float* __restrict__ q, const float* __restrict__ k, const float* __restrict__ v,
    const __half* __restrict__ Wt,
    __half* __restrict__ Qph, __half* __restrict__ Qpl,
    __half* __restrict__ Kph, __half* __restrict__ Kpl,
    __half* __restrict__ Vph, __half* __restrict__ Vpl)
{
    const int bid = blockIdx.x;
    const size_t WSZ = (size_t)DMODEL * DMODEL;
    const float* A; const __half* B; __half *Ch, *Cl; int t;
    if (bid < 256)      { A = q; B = Wt;           Ch = Qph; Cl = Qpl; t = bid; }
    else if (bid < 320) { A = k; B = Wt + WSZ;     Ch = Kph; Cl = Kpl; t = bid - 256; }
    else                { A = v; B = Wt + 2 * WSZ; Ch = Vph; Cl = Vpl; t = bid - 320; }
    gemm_pipe_tile<true, true>(A, nullptr, nullptr, B, nullptr, Ch, Cl,
                               (t >> 2) * 128, (t & 3) * 128);
}

__global__ __launch_bounds__(256, 2) void outproj_kernel(
    const __half* __restrict__ ch, const __half* __restrict__ cl,
    const __half* __restrict__ Wt, float* __restrict__ out)
{
    const size_t WSZ = (size_t)DMODEL * DMODEL;
    gemm_pipe_tile<false, false>(nullptr, ch, cl, Wt + 3 * WSZ,
                                 out, nullptr, nullptr,
                                 blockIdx.y * 128, blockIdx.x * 128);
}

// ---------------- tensor-core sparse attention (fp16 3-term) ----------------
#define AROWB 144
#define SQH 0
#define SQL (SQH + 64 * AROWB)
#define SKH (SQL + 64 * AROWB)
#define SKL (SKH + 32 * AROWB)
#define SVH (SKL + 32 * AROWB)
#define SVL (SVH + 32 * AROWB)
#define ATT_SM (SVL + 32 * AROWB)

__global__ __launch_bounds__(128) void attn_tc_kernel(
    const __half* __restrict__ Qph, const __half* __restrict__ Qpl,
    const __half* __restrict__ Kph, const __half* __restrict__ Kpl,
    const __half* __restrict__ Vph, const __half* __restrict__ Vpl,
    __half* __restrict__ ctxh, __half* __restrict__ ctxl)
{
    __shared__ char sm[ATT_SM];
    const uint32_t sb = smem_u32(sm);
    const int c0  = blockIdx.x * 64;
    const int h   = blockIdx.y;
    const int b   = blockIdx.z;
    const int tid = threadIdx.x;
    const int wid = tid >> 5;
    const int lane = tid & 31;

    int jmin = (c0 - (SPAN - 1) + (STRIDE - 1)) >> 2;
    if (jmin < 0) jmin = 0;
    int jmax = (c0 + 63) >> 2;
    if (jmax > LKV - 1) jmax = LKV - 1;
    const int nrows = jmax - jmin + 1;

    for (int u = tid; u < (32 - nrows) * 36; u += 128) {
        const int r = nrows + u / 36, w = u % 36;
        ((uint32_t*)(sm + SVH))[r * 36 + w] = 0;
        ((uint32_t*)(sm + SVL))[r * 36 + w] = 0;
    }
    for (int u = tid; u < 512; u += 128) {
        const int r = u >> 3, cb = (u & 7) << 4;
        const size_t gb = (size_t)(b * LQ + c0 + r) * (DMODEL * 2) + h * DHEAD * 2 + cb;
        *(uint4*)(sm + SQH + r * AROWB + cb) = *(const uint4*)((const char*)Qph + gb);
        *(uint4*)(sm + SQL + r * AROWB + cb) = *(const uint4*)((const char*)Qpl + gb);
    }
    for (int u = tid; u < nrows * 8; u += 128) {
        const int r = u >> 3, cb = (u & 7) << 4;
        const size_t gb = (size_t)(b * LKV + jmin + r) * (DMODEL * 2) + h * DHEAD * 2 + cb;
        *(uint4*)(sm + SKH + r * AROWB + cb) = *(const uint4*)((const char*)Kph + gb);
        *(uint4*)(sm + SKL + r * AROWB + cb) = *(const uint4*)((const char*)Kpl + gb);
        *(uint4*)(sm + SVH + r * AROWB + cb) = *(const uint4*)((const char*)Vph + gb);
        *(uint4*)(sm + SVL + r * AROWB + cb) = *(const uint4*)((const char*)Vpl + gb);
    }
    __syncthreads();

    float s[4][4];
    #pragma unroll
    for (int ni = 0; ni < 4; ni++)
        #pragma unroll
        for (int e = 0; e < 4; e++) s[ni][e] = 0.0f;

    const uint32_t qa = sb + (uint32_t)(wid * 16 + (lane & 15)) * AROWB + ((lane >> 4) << 4);
    const uint32_t kb = sb + SKH + (uint32_t)(lane & 7) * AROWB + (((lane >> 3) & 1) << 4);
    #pragma unroll
    for (int ks = 0; ks < 4; ks++) {
        const uint32_t ko = (uint32_t)ks * 32;
        uint32_t qh4[4], ql4[4], b2[2];
        ldsm_x4(qh4, qa + SQH + ko);
        ldsm_x4(ql4, qa + SQL + ko);
        #pragma unroll
        for (int ni = 0; ni < 4; ni++) {
            const uint32_t bo = kb + (uint32_t)(ni * 8) * AROWB + ko;
            ldsm_x2(b2, bo);
            mma_f16(s[ni], qh4, b2);
            mma_f16(s[ni], ql4, b2);
            ldsm_x2(b2, bo + (SKL - SKH));
            mma_f16(s[ni], qh4, b2);
        }
    }

    const int r_lo = c0 + wid * 16 + (lane >> 2);
    const int r_hi = r_lo + 8;
    #pragma unroll
    for (int ni = 0; ni < 4; ni++) {
        #pragma unroll
        for (int e = 0; e < 4; e++) {
            const int col_abs = jmin + ni * 8 + (lane & 3) * 2 + (e & 1);
            const int c = (e < 2) ? r_lo : r_hi;
            const bool valid = (unsigned)(c - 4 * col_abs) < (unsigned)SPAN;
            s[ni][e] = valid ? s[ni][e] * 0.125f : -1e30f;
        }
    }

    float mx0 = -1e30f, mx1 = -1e30f;
    #pragma unroll
    for (int ni = 0; ni < 4; ni++) {
        mx0 = fmaxf(mx0, fmaxf(s[ni][0], s[ni][1]));
        mx1 = fmaxf(mx1, fmaxf(s[ni][2], s[ni][3]));
    }
    mx0 = fmaxf(mx0, __shfl_xor_sync(0xffffffffu, mx0, 1));
    mx0 = fmaxf(mx0, __shfl_xor_sync(0xffffffffu, mx0, 2));
    mx1 = fmaxf(mx1, __shfl_xor_sync(0xffffffffu, mx1, 1));
    mx1 = fmaxf(mx1, __shfl_xor_sync(0xffffffffu, mx1, 2));
    float sum0 = 0.0f, sum1 = 0.0f;
    #pragma unroll
    for (int ni = 0; ni < 4; ni++) {
        s[ni][0] = __expf(s[ni][0] - mx0); sum0 += s[ni][0];
        s[ni][1] = __expf(s[ni][1] - mx0); sum0 += s[ni][1];
        s[ni][2] = __expf(s[ni][2] - mx1); sum1 += s[ni][2];
        s[ni][3] = __expf(s[ni][3] - mx1); sum1 += s[ni][3];
    }
    sum0 += __shfl_xor_sync(0xffffffffu, sum0, 1);
    sum0 += __shfl_xor_sync(0xffffffffu, sum0, 2);
    sum1 += __shfl_xor_sync(0xffffffffu, sum1, 1);
    sum1 += __shfl_xor_sync(0xffffffffu, sum1, 2);
    const float inv0 = 1.0f / sum0, inv1 = 1.0f / sum1;
    #pragma unroll
    for (int ni = 0; ni < 4; ni++) {
        s[ni][0] *= inv0; s[ni][1] *= inv0;
        s[ni][2] *= inv1; s[ni][3] *= inv1;
    }

    uint32_t aPh[2][4], aPl[2][4];
    #pragma unroll
    for (int kc = 0; kc < 2; kc++) {
        #pragma unroll
        for (int half = 0; half < 2; half++) {
            const float* p = s[2 * kc + half];
            float lo0 = p[0] - __half2float(__float2half_rn(p[0]));
            float lo1 = p[1] - __half2float(__float2half_rn(p[1]));
            float lo2 = p[2] - __half2float(__float2half_rn(p[2]));
            float lo3 = p[3] - __half2float(__float2half_rn(p[3]));
            aPh[kc][half * 2 + 0] = pack_h2(p[0], p[1]);
            aPh[kc][half * 2 + 1] = pack_h2(p[2], p[3]);
            aPl[kc][half * 2 + 0] = pack_h2(lo0, lo1);
            aPl[kc][half * 2 + 1] = pack_h2(lo2, lo3);
        }
    }

    float o[8][4];
    #pragma unroll
    for (int ni = 0; ni < 8; ni++)
        #pragma unroll
        for (int e = 0; e < 4; e++) o[ni][e] = 0.0f;
    const uint32_t vrow = (uint32_t)((lane & 7) + ((lane >> 3) & 1) * 8) * AROWB;
    #pragma unroll
    for (int kc = 0; kc < 2; kc++) {
        const uint32_t kro = (uint32_t)(kc * 16) * AROWB;
        #pragma unroll
        for (int ni = 0; ni < 8; ni++) {
            uint32_t b2[2];
            const uint32_t bo = kro + vrow + (uint32_t)(ni * 16);
            ldsm_x2_trans(b2, sb + SVH + bo);
            mma_f16(o[ni], aPh[kc], b2);
            mma_f16(o[ni], aPl[kc], b2);
            ldsm_x2_trans(b2, sb + SVL + bo);
            mma_f16(o[ni], aPh[kc], b2);
        }
    }

    #pragma unroll
    for (int ni = 0; ni < 8; ni++) {
        const int col = ni * 8 + (lane & 3) * 2;
        const size_t i0 = (size_t)(b * LQ + r_lo) * DMODEL + h * DHEAD + col;
        const size_t i1 = (size_t)(b * LQ + r_hi) * DMODEL + h * DHEAD + col;
        __half h0, h1, h2, h3, l0, l1, l2, l3;
        h_split(o[ni][0], h0, l0); h_split(o[ni][1], h1, l1);
        h_split(o[ni][2], h2, l2); h_split(o[ni][3], h3, l3);
        *(__half2*)&ctxh[i0] = __half2(h0, h1);
        *(__half2*)&ctxl[i0] = __half2(l0, l1);
        *(__half2*)&ctxh[i1] = __half2(h2, h3);
        *(__half2*)&ctxl[i1] = __half2(l2, l3);
    }
}

// ---------------- launch ----------------
extern "C" void kernel_launch(void* const* d_in, const int* in_sizes, int n_in,
                              void* d_out, int out_size)
{
    const float* q    = (const float*)d_in[0];
    const float* k    = (const float*)d_in[1];
    const float* v    = (const float*)d_in[2];
    const float* Wq   = (const float*)d_in[3];
    const float* Wk   = (const float*)d_in[4];
    const float* Wv   = (const float*)d_in[5];
    const float* Wout = (const float*)d_in[6];
    float* out = (float*)d_out;

    __half *Qph, *Qpl, *Kph, *Kpl, *Vph, *Vpl, *ch, *cl, *Wt;
    cudaGetSymbolAddress((void**)&Qph, g_Qph); cudaGetSymbolAddress((void**)&Qpl, g_Qpl);
    cudaGetSymbolAddress((void**)&Kph, g_Kph); cudaGetSymbolAddress((void**)&Kpl, g_Kpl);
    cudaGetSymbolAddress((void**)&Vph, g_Vph); cudaGetSymbolAddress((void**)&Vpl, g_Vpl);
    cudaGetSymbolAddress((void**)&ch,  g_ch);  cudaGetSymbolAddress((void**)&cl,  g_cl);
    cudaGetSymbolAddress((void**)&Wt,  g_Wt);

    cudaFuncSetAttribute(proj_fused_kernel,
                         cudaFuncAttributeMaxDynamicSharedMemorySize, GEMM_SMEM);
    cudaFuncSetAttribute(outproj_kernel,
                         cudaFuncAttributeMaxDynamicSharedMemorySize, GEMM_SMEM);

    split_w_kernel<<<dim3(16, 16, 4), dim3(32, 32)>>>(Wq, Wk, Wv, Wout, Wt);
    proj_fused_kernel<<<384, 256, GEMM_SMEM>>>(q, k, v, Wt,
                                               Qph, Qpl, Kph, Kpl, Vph, Vpl);
    attn_tc_kernel<<<dim3(LQ / 64, HEADS, B_SZ), 128>>>(Qph, Qpl, Kph, Kpl, Vph, Vpl, ch, cl);
    outproj_kernel<<<dim3(4, 64), 256, GEMM_SMEM>>>(ch, cl, Wt, out);
}

// round 9
// speedup vs baseline: 1.7958x; 1.0290x over previous
#include <cuda_runtime.h>
#include <cuda_fp16.h>
#include <cstdint>

#define B_SZ   2
#define LQ     4096
#define LKV    1024
#define DMODEL 512
#define HEADS  8
#define DHEAD  64
#define SPAN   64
#define STRIDE 4

#define MQ (B_SZ * LQ)    // 8192
#define MK (B_SZ * LKV)   // 2048

// ---------------- scratch ----------------
__device__ __half g_Qph[MQ * DMODEL], g_Qpl[MQ * DMODEL];
__device__ __half g_Kp [MK * DMODEL];             // single fp16
__device__ __half g_Vp [MK * DMODEL];             // single fp16
__device__ __half g_ch[MQ * DMODEL], g_cl[MQ * DMODEL];
__device__ __half g_Wt[4 * DMODEL * DMODEL];      // transposed single-fp16 weights

// ---------------- helpers ----------------
__device__ __forceinline__ uint32_t smem_u32(const void* p) {
    uint32_t a;
    asm("{ .reg .u64 t; cvta.to.shared.u64 t, %1; cvt.u32.u64 %0, t; }" : "=r"(a) : "l"(p));
    return a;
}
__device__ __forceinline__ void h_split(float x, __half& h, __half& l) {
    h = __float2half_rn(x);
    l = __float2half_rn(x - __half2float(h));
}
__device__ __forceinline__ uint32_t pack_h2(float a, float b) {
    __half2 t(__float2half_rn(a), __float2half_rn(b));
    return *(uint32_t*)&t;
}
__device__ __forceinline__ void ldsm_x4(uint32_t* r, uint32_t a) {
    asm volatile("ldmatrix.sync.aligned.m8n8.x4.shared.b16 {%0,%1,%2,%3}, [%4];"
        : "=r"(r[0]), "=r"(r[1]), "=r"(r[2]), "=r"(r[3]) : "r"(a));
}
__device__ __forceinline__ void ldsm_x2(uint32_t* r, uint32_t a) {
    asm volatile("ldmatrix.sync.aligned.m8n8.x2.shared.b16 {%0,%1}, [%2];"
        : "=r"(r[0]), "=r"(r[1]) : "r"(a));
}
__device__ __forceinline__ void ldsm_x2_trans(uint32_t* r, uint32_t a) {
    asm volatile("ldmatrix.sync.aligned.m8n8.x2.trans.shared.b16 {%0,%1}, [%2];"
        : "=r"(r[0]), "=r"(r[1]) : "r"(a));
}
__device__ __forceinline__ void mma_f16(float* c, const uint32_t* a, const uint32_t* b) {
    asm volatile(
        "mma.sync.aligned.m16n8k16.row.col.f32.f16.f16.f32 "
        "{%0,%1,%2,%3}, {%4,%5,%6,%7}, {%8,%9}, {%0,%1,%2,%3};"
        : "+f"(c[0]), "+f"(c[1]), "+f"(c[2]), "+f"(c[3])
        : "r"(a[0]), "r"(a[1]), "r"(a[2]), "r"(a[3]), "r"(b[0]), "r"(b[1]));
}
__device__ __forceinline__ void cp16(uint32_t dst, const void* src) {
    asm volatile("cp.async.cg.shared.global [%0], [%1], 16;" :: "r"(dst), "l"(src));
}
#define CP_COMMIT() asm volatile("cp.async.commit_group;" ::: "memory")
#define CP_WAIT0()  asm volatile("cp.async.wait_group 0;" ::: "memory")
#define CP_WAIT1()  asm volatile("cp.async.wait_group 1;" ::: "memory")

// ---------------- prepass: transpose weights to single fp16 ----------------
__global__ __launch_bounds__(1024) void split_w_kernel(
    const float* __restrict__ W0, const float* __restrict__ W1,
    const float* __restrict__ W2, const float* __restrict__ W3,
    __half* __restrict__ Wt)
{
    __shared__ float t[32][33];
    const int z = blockIdx.z;
    const float* W = (z == 0) ? W0 : (z == 1) ? W1 : (z == 2) ? W2 : W3;
    const int n0 = blockIdx.x * 32, k0 = blockIdx.y * 32;
    const int tx = threadIdx.x, ty = threadIdx.y;
    t[ty][tx] = W[(size_t)(k0 + ty) * DMODEL + n0 + tx];
    __syncthreads();
    size_t o = (size_t)z * DMODEL * DMODEL + (size_t)(n0 + ty) * DMODEL + k0 + tx;
    Wt[o] = __float2half_rn(t[tx][ty]);
}

// ---------------- 3-stage cp.async 2-term fp16 GEMM ----------------
// C[128,128] = A[128,512] @ Bt[128,512]^T ; A split hi/lo fp16, B single fp16.
// outmode: 0 = fp32 out, 1 = split hi/lo fp16 out, 2 = single fp16 out
#define GROWB 80
#define GTSZ  (128 * GROWB)        // 10240
#define STG   (3 * GTSZ)           // 30720 per stage (Ah | Al | B)
#define NSTG  3
#define GEMM_SMEM (NSTG * STG)     // 92160
#define NCH   16                   // 512 / 32

template<bool AFP32>
__device__ __forceinline__ void gemm_pipe_tile(
    const float* __restrict__ A32,
    const __half* __restrict__ Ah, const __half* __restrict__ Al,
    const __half* __restrict__ B,
    float* __restrict__ Cf, __half* __restrict__ Ch, __half* __restrict__ Cl,
    int row0, int col0, int outmode)
{
    extern __shared__ char sm[];
    const uint32_t sb = smem_u32(sm);
    const int tid  = threadIdx.x;
    const int wid  = tid >> 5;
    const int lane = tid & 31;
    const int m0 = (wid & 1) * 64;
    const int n0 = (wid >> 1) * 32;

    float acc[4][4][4];
    #pragma unroll
    for (int mi = 0; mi < 4; mi++)
        #pragma unroll
        for (int ni = 0; ni < 4; ni++)
            #pragma unroll
            for (int e = 0; e < 4; e++) acc[mi][ni][e] = 0.0f;

    const uint32_t a_off = (uint32_t)(m0 + (lane & 15)) * GROWB + ((lane >> 4) << 4);
    const uint32_t b_off = (uint32_t)((lane & 7) + ((lane >> 4) & 1) * 8) * GROWB
                         + (((lane >> 3) & 1) << 4);

    const int ir0 = (tid + 0)   >> 2, ic0 = ((tid + 0)   & 3) << 4;
    const int ir1 = (tid + 256) >> 2, ic1 = ((tid + 256) & 3) << 4;

    float ar[2][8];

    auto ldA_regs = [&](int ch) {
        if (!AFP32) return;
        const int kc = ch * 32;
        {
            const float* pa = A32 + (size_t)(row0 + ir0) * DMODEL + kc + (ic0 >> 1);
            float4 x = *(const float4*)pa, y = *(const float4*)(pa + 4);
            ar[0][0]=x.x; ar[0][1]=x.y; ar[0][2]=x.z; ar[0][3]=x.w;
            ar[0][4]=y.x; ar[0][5]=y.y; ar[0][6]=y.z; ar[0][7]=y.w;
        }
        {
            const float* pa = A32 + (size_t)(row0 + ir1) * DMODEL + kc + (ic1 >> 1);
            float4 x = *(const float4*)pa, y = *(const float4*)(pa + 4);
            ar[1][0]=x.x; ar[1][1]=x.y; ar[1][2]=x.z; ar[1][3]=x.w;
            ar[1][4]=y.x; ar[1][5]=y.y; ar[1][6]=y.z; ar[1][7]=y.w;
        }
    };
    auto stsA = [&](int buf) {
        if (!AFP32) return;
        #pragma unroll
        for (int p = 0; p < 2; p++) {
            const int ir = p ? ir1 : ir0;
            const int ic = p ? ic1 : ic0;
            const float* a = ar[p];
            uint4 hi, lo;
            hi.x = pack_h2(a[0], a[1]); hi.y = pack_h2(a[2], a[3]);
            hi.z = pack_h2(a[4], a[5]); hi.w = pack_h2(a[6], a[7]);
            float l0 = a[0] - __half2float(__float2half_rn(a[0]));
            float l1 = a[1] - __half2float(__float2half_rn(a[1]));
            float l2 = a[2] - __half2float(__float2half_rn(a[2]));
            float l3 = a[3] - __half2float(__float2half_rn(a[3]));
            float l4 = a[4] - __half2float(__float2half_rn(a[4]));
            float l5 = a[5] - __half2float(__float2half_rn(a[5]));
            float l6 = a[6] - __half2float(__float2half_rn(a[6]));
            float l7 = a[7] - __half2float(__float2half_rn(a[7]));
            lo.x = pack_h2(l0, l1); lo.y = pack_h2(l2, l3);
            lo.z = pack_h2(l4, l5); lo.w = pack_h2(l6, l7);
            const uint32_t dso = (uint32_t)ir * GROWB + ic + (uint32_t)buf * STG;
            *(uint4*)(sm + 0 * GTSZ + dso) = hi;
            *(uint4*)(sm + 1 * GTSZ + dso) = lo;
        }
    };
    auto issue_cp = [&](int ch, int buf) {
        const uint32_t stg = sb + (uint32_t)buf * STG;
        const size_t kb = (size_t)ch * 64;
        #pragma unroll
        for (int p = 0; p < 2; p++) {
            const int ir = p ? ir1 : ir0;
            const int ic = p ? ic1 : ic0;
            const uint32_t dso = (uint32_t)ir * GROWB + ic;
            const size_t gb = (size_t)(col0 + ir) * (DMODEL * 2) + kb + ic;
            cp16(stg + 2 * GTSZ + dso, (const char*)B + gb);
            if (!AFP32) {
                const size_t ga = (size_t)(row0 + ir) * (DMODEL * 2) + kb + ic;
                cp16(stg + 0 * GTSZ + dso, (const char*)Ah + ga);
                cp16(stg + 1 * GTSZ + dso, (const char*)Al + ga);
            }
        }
        CP_COMMIT();
    };

    ldA_regs(0);
    issue_cp(0, 0);
    issue_cp(1, 1);

    for (int ch = 0; ch < NCH; ch++) {
        if (ch + 1 < NCH) CP_WAIT1(); else CP_WAIT0();   // stage ch complete
        __syncthreads();                 // all warps past compute(ch-1)
        stsA(ch % NSTG);
        if (AFP32 && ch + 1 < NCH) ldA_regs(ch + 1);
        if (ch + 2 < NCH) issue_cp(ch + 2, (ch + 2) % NSTG);
        if (AFP32) __syncthreads();      // A STS visible to all warps

        const uint32_t stg = sb + (uint32_t)(ch % NSTG) * STG;
        const uint32_t aH = stg + 0 * GTSZ + a_off;
        const uint32_t aL = stg + 1 * GTSZ + a_off;
        const uint32_t bB = stg + 2 * GTSZ + b_off + (uint32_t)n0 * GROWB;

        #pragma unroll
        for (int ks = 0; ks < 2; ks++) {
            const uint32_t ko = (uint32_t)ks * 32;
            uint32_t bf[2][4], af[4][4];
            ldsm_x4(bf[0], bB + ko);
            ldsm_x4(bf[1], bB + (uint32_t)(16 * GROWB) + ko);
            #pragma unroll
            for (int mi = 0; mi < 4; mi++)
                ldsm_x4(af[mi], aH + (uint32_t)(mi * 16) * GROWB + ko);
            #pragma unroll
            for (int nj = 0; nj < 2; nj++)
                #pragma unroll
                for (int mi = 0; mi < 4; mi++) {
                    mma_f16(acc[mi][2 * nj + 0], af[mi], bf[nj] + 0);
                    mma_f16(acc[mi][2 * nj + 1], af[mi], bf[nj] + 2);
                }
            #pragma unroll
            for (int mi = 0; mi < 4; mi++)
                ldsm_x4(af[mi], aL + (uint32_t)(mi * 16) * GROWB + ko);
            #pragma unroll
            for (int nj = 0; nj < 2; nj++)
                #pragma unroll
                for (int mi = 0; mi < 4; mi++) {
                    mma_f16(acc[mi][2 * nj + 0], af[mi], bf[nj] + 0);
                    mma_f16(acc[mi][2 * nj + 1], af[mi], bf[nj] + 2);
                }
        }
    }

    #pragma unroll
    for (int mi = 0; mi < 4; mi++) {
        #pragma unroll
        for (int ni = 0; ni < 4; ni++) {
            const int row = row0 + m0 + mi * 16 + (lane >> 2);
            const int col = col0 + n0 + ni * 8 + (lane & 3) * 2;
            const float* a = acc[mi][ni];
            if (outmode == 1) {
                __half h0, h1, h2, h3, l0, l1, l2, l3;
                h_split(a[0], h0, l0); h_split(a[1], h1, l1);
                h_split(a[2], h2, l2); h_split(a[3], h3, l3);
                *(__half2*)&Ch[(size_t)row * DMODEL + col] = __half2(h0, h1);
                *(__half2*)&Cl[(size_t)row * DMODEL + col] = __half2(l0, l1);
                *(__half2*)&Ch[(size_t)(row + 8) * DMODEL + col] = __half2(h2, h3);
                *(__half2*)&Cl[(size_t)(row + 8) * DMODEL + col] = __half2(l2, l3);
            } else if (outmode == 2) {
                *(__half2*)&Ch[(size_t)row * DMODEL + col] =
                    __half2(__float2half_rn(a[0]), __float2half_rn(a[1]));
                *(__half2*)&Ch[(size_t)(row + 8) * DMODEL + col] =
                    __half2(__float2half_rn(a[2]), __float2half_rn(a[3]));
            } else {
                *(float2*)&Cf[(size_t)row * DMODEL + col] = make_float2(a[0], a[1]);
                *(float2*)&Cf[(size_t)(row + 8) * DMODEL + col] = make_float2(a[2], a[3]);
            }
        }
    }
}

__global__ __launch_bounds__(256, 2) void proj_fused_kernel(
    const float* __restrict__ q, const float* __restrict__ k, const float* __restrict__ v,
    const __half* __restrict__ Wt,
    __half* __restrict__ Qph, __half* __restrict__ Qpl,
    __half* __restrict__ Kp, __half* __restrict__ Vp)
{
    const int bid = blockIdx.x;
    const size_t WSZ = (size_t)DMODEL * DMODEL;
    const float* A; const __half* B; __half *Ch, *Cl; int t, mode;
    if (bid < 256)      { A = q; B = Wt;           Ch = Qph; Cl = Qpl;     t = bid;       mode = 1; }
    else if (bid < 320) { A = k; B = Wt + WSZ;     Ch = Kp;  Cl = nullptr; t = bid - 256; mode = 2; }
    else                { A = v; B = Wt + 2 * WSZ; Ch = Vp;  Cl = nullptr; t = bid - 320; mode = 2; }
    gemm_pipe_tile<true>(A, nullptr, nullptr, B, nullptr, Ch, Cl,
                         (t >> 2) * 128, (t & 3) * 128, mode);
}

__global__ __launch_bounds__(256, 2) void outproj_kernel(
    const __half* __restrict__ ch, const __half* __restrict__ cl,
    const __half* __restrict__ Wt, float* __restrict__ out)
{
    const size_t WSZ = (size_t)DMODEL * DMODEL;
    gemm_pipe_tile<false>(nullptr, ch, cl, Wt + 3 * WSZ,
                          out, nullptr, nullptr,
                          blockIdx.y * 128, blockIdx.x * 128, 0);
}

// ---------------- tensor-core sparse attention (Q hi/lo, K/V single fp16) ----------------
#define AROWB 144
#define SQH 0
#define SQL (SQH + 64 * AROWB)      // 9216
#define SK  (SQL + 64 * AROWB)      // 18432
#define SV  (SK + 32 * AROWB)       // 23040
#define ATT_SM (SV + 32 * AROWB)    // 27648

__global__ __launch_bounds__(128) void attn_tc_kernel(
    const __half* __restrict__ Qph, const __half* __restrict__ Qpl,
    const __half* __restrict__ Kp, const __half* __restrict__ Vp,
    __half* __restrict__ ctxh, __half* __restrict__ ctxl)
{
    __shared__ char sm[ATT_SM];
    const uint32_t sb = smem_u32(sm);
    const int c0  = blockIdx.x * 64;
    const int h   = blockIdx.y;
    const int b   = blockIdx.z;
    const int tid = threadIdx.x;
    const int wid = tid >> 5;
    const int lane = tid & 31;

    int jmin = (c0 - (SPAN - 1) + (STRIDE - 1)) >> 2;
    if (jmin < 0) jmin = 0;
    int jmax = (c0 + 63) >> 2;
    if (jmax > LKV - 1) jmax = LKV - 1;
    const int nrows = jmax - jmin + 1;                  // <= 32

    // zero V tail rows (weight-0 rows must not be NaN)
    for (int u = tid; u < (32 - nrows) * 36; u += 128) {
        const int r = nrows + u / 36, w = u % 36;
        ((uint32_t*)(sm + SV))[r * 36 + w] = 0;
    }
    // Q tile hi+lo (64 rows x 128B)
    for (int u = tid; u < 512; u += 128) {
        const int r = u >> 3, cb = (u & 7) << 4;
        const size_t gb = (size_t)(b * LQ + c0 + r) * (DMODEL * 2) + h * DHEAD * 2 + cb;
        *(uint4*)(sm + SQH + r * AROWB + cb) = *(const uint4*)((const char*)Qph + gb);
        *(uint4*)(sm + SQL + r * AROWB + cb) = *(const uint4*)((const char*)Qpl + gb);
    }
    // K + V window rows (single fp16, row-major)
    for (int u = tid; u < nrows * 8; u += 128) {
        const int r = u >> 3, cb = (u & 7) << 4;
        const size_t gb = (size_t)(b * LKV + jmin + r) * (DMODEL * 2) + h * DHEAD * 2 + cb;
        *(uint4*)(sm + SK + r * AROWB + cb) = *(const uint4*)((const char*)Kp + gb);
        *(uint4*)(sm + SV + r * AROWB + cb) = *(const uint4*)((const char*)Vp + gb);
    }
    __syncthreads();

    // ---- S = Q @ K^T (2-term: Qh*K + Ql*K) ----
    float s[4][4];
    #pragma unroll
    for (int ni = 0; ni < 4; ni++)
        #pragma unroll
        for (int e = 0; e < 4; e++) s[ni][e] = 0.0f;

    const uint32_t qa = sb + (uint32_t)(wid * 16 + (lane & 15)) * AROWB + ((lane >> 4) << 4);
    const uint32_t kb = sb + SK + (uint32_t)(lane & 7) * AROWB + (((lane >> 3) & 1) << 4);
    #pragma unroll
    for (int ks = 0; ks < 4; ks++) {
        const uint32_t ko = (uint32_t)ks * 32;
        uint32_t qh4[4], ql4[4], b2[2];
        ldsm_x4(qh4, qa + SQH + ko);
        ldsm_x4(ql4, qa + SQL + ko);
        #pragma unroll
        for (int ni = 0; ni < 4; ni++) {
            ldsm_x2(b2, kb + (uint32_t)(ni * 8) * AROWB + ko);
            mma_f16(s[ni], qh4, b2);
            mma_f16(s[ni], ql4, b2);
        }
    }

    // ---- mask + scale ----
    const int r_lo = c0 + wid * 16 + (lane >> 2);
    const int r_hi = r_lo + 8;
    #pragma unroll
    for (int ni = 0; ni < 4; ni++) {
        #pragma unroll
        for (int e = 0; e < 4; e++) {
            const int col_abs = jmin + ni * 8 + (lane & 3) * 2 + (e & 1);
            const int c = (e < 2) ? r_lo : r_hi;
            const bool valid = (unsigned)(c - 4 * col_abs) < (unsigned)SPAN;
            s[ni][e] = valid ? s[ni][e] * 0.125f : -1e30f;
        }
    }

    // ---- softmax over quad ----
    float mx0 = -1e30f, mx1 = -1e30f;
    #pragma unroll
    for (int ni = 0; ni < 4; ni++) {
        mx0 = fmaxf(mx0, fmaxf(s[ni][0], s[ni][1]));
        mx1 = fmaxf(mx1, fmaxf(s[ni][2], s[ni][3]));
    }
    mx0 = fmaxf(mx0, __shfl_xor_sync(0xffffffffu, mx0, 1));
    mx0 = fmaxf(mx0, __shfl_xor_sync(0xffffffffu, mx0, 2));
    mx1 = fmaxf(mx1, __shfl_xor_sync(0xffffffffu, mx1, 1));
    mx1 = fmaxf(mx1, __shfl_xor_sync(0xffffffffu, mx1, 2));
    float sum0 = 0.0f, sum1 = 0.0f;
    #pragma unroll
    for (int ni = 0; ni < 4; ni++) {
        s[ni][0] = __expf(s[ni][0] - mx0); sum0 += s[ni][0];
        s[ni][1] = __expf(s[ni][1] - mx0); sum0 += s[ni][1];
        s[ni][2] = __expf(s[ni][2] - mx1); sum1 += s[ni][2];
        s[ni][3] = __expf(s[ni][3] - mx1); sum1 += s[ni][3];
    }
    sum0 += __shfl_xor_sync(0xffffffffu, sum0, 1);
    sum0 += __shfl_xor_sync(0xffffffffu, sum0, 2);
    sum1 += __shfl_xor_sync(0xffffffffu, sum1, 1);
    sum1 += __shfl_xor_sync(0xffffffffu, sum1, 2);
    const float inv0 = 1.0f / sum0, inv1 = 1.0f / sum1;
    #pragma unroll
    for (int ni = 0; ni < 4; ni++) {
        s[ni][0] *= inv0; s[ni][1] *= inv0;
        s[ni][2] *= inv1; s[ni][3] *= inv1;
    }

    // ---- pack P frags (hi + lo) ----
    uint32_t aPh[2][4], aPl[2][4];
    #pragma unroll
    for (int kc = 0; kc < 2; kc++) {
        #pragma unroll
        for (int half = 0; half < 2; half++) {
            const float* p = s[2 * kc + half];
            float lo0 = p[0] - __half2float(__float2half_rn(p[0]));
            float lo1 = p[1] - __half2float(__float2half_rn(p[1]));
            float lo2 = p[2] - __half2float(__float2half_rn(p[2]));
            float lo3 = p[3] - __half2float(__float2half_rn(p[3]));
            aPh[kc][half * 2 + 0] = pack_h2(p[0], p[1]);
            aPh[kc][half * 2 + 1] = pack_h2(p[2], p[3]);
            aPl[kc][half * 2 + 0] = pack_h2(lo0, lo1);
            aPl[kc][half * 2 + 1] = pack_h2(lo2, lo3);
        }
    }

    // ---- O = P @ V (V single fp16, B-frags via ldmatrix.trans) ----
    float o[8][4];
    #pragma unroll
    for (int ni = 0; ni < 8; ni++)
        #pragma unroll
        for (int e = 0; e < 4; e++) o[ni][e] = 0.0f;
    const uint32_t vrow = (uint32_t)((lane & 7) + ((lane >> 3) & 1) * 8) * AROWB;
    #pragma unroll
    for (int kc = 0; kc < 2; kc++) {
        const uint32_t kro = (uint32_t)(kc * 16) * AROWB;
        #pragma unroll
        for (int ni = 0; ni < 8; ni++) {
            uint32_t b2[2];
            ldsm_x2_trans(b2, sb + SV + kro + vrow + (uint32_t)(ni * 16));
            mma_f16(o[ni], aPh[kc], b2);
            mma_f16(o[ni], aPl[kc], b2);
        }
    }

    // ---- store ctx hi/lo ----
    #pragma unroll
    for (int ni = 0; ni < 8; ni++) {
        const int col = ni * 8 + (lane & 3) * 2;
        const size_t i0 = (size_t)(b * LQ + r_lo) * DMODEL + h * DHEAD + col;
        const size_t i1 = (size_t)(b * LQ + r_hi) * DMODEL + h * DHEAD + col;
        __half h0, h1, h2, h3, l0, l1, l2, l3;
        h_split(o[ni][0], h0, l0); h_split(o[ni][1], h1, l1);
        h_split(o[ni][2], h2, l2); h_split(o[ni][3], h3, l3);
        *(__half2*)&ctxh[i0] = __half2(h0, h1);
        *(__half2*)&ctxl[i0] = __half2(l0, l1);
        *(__half2*)&ctxh[i1] = __half2(h2, h3);
        *(__half2*)&ctxl[i1] = __half2(l2, l3);
    }
}

// ---------------- launch ----------------
extern "C" void kernel_launch(void* const* d_in, const int* in_sizes, int n_in,
                              void* d_out, int out_size)
{
    const float* q    = (const float*)d_in[0];
    const float* k    = (const float*)d_in[1];
    const float* v    = (const float*)d_in[2];
    const float* Wq   = (const float*)d_in[3];
    const float* Wk   = (const float*)d_in[4];
    const float* Wv   = (const float*)d_in[5];
    const float* Wout = (const float*)d_in[6];
    float* out = (float*)d_out;

    __half *Qph, *Qpl, *Kp, *Vp, *ch, *cl, *Wt;
    cudaGetSymbolAddress((void**)&Qph, g_Qph); cudaGetSymbolAddress((void**)&Qpl, g_Qpl);
    cudaGetSymbolAddress((void**)&Kp,  g_Kp);  cudaGetSymbolAddress((void**)&Vp,  g_Vp);
    cudaGetSymbolAddress((void**)&ch,  g_ch);  cudaGetSymbolAddress((void**)&cl,  g_cl);
    cudaGetSymbolAddress((void**)&Wt,  g_Wt);

    cudaFuncSetAttribute(proj_fused_kernel,
                         cudaFuncAttributeMaxDynamicSharedMemorySize, GEMM_SMEM);
    cudaFuncSetAttribute(outproj_kernel,
                         cudaFuncAttributeMaxDynamicSharedMemorySize, GEMM_SMEM);

    split_w_kernel<<<dim3(16, 16, 4), dim3(32, 32)>>>(Wq, Wk, Wv, Wout, Wt);
    proj_fused_kernel<<<384, 256, GEMM_SMEM>>>(q, k, v, Wt, Qph, Qpl, Kp, Vp);
    attn_tc_kernel<<<dim3(LQ / 64, HEADS, B_SZ), 128>>>(Qph, Qpl, Kp, Vp, ch, cl);
    outproj_kernel<<<dim3(4, 64), 256, GEMM_SMEM>>>(ch, cl, Wt, out);
}

// round 10
// speedup vs baseline: 2.3267x; 1.2956x over previous
#include <cuda_runtime.h>
#include <cuda_fp16.h>
#include <cstdint>

#define B_SZ   2
#define LQ     4096
#define LKV    1024
#define DMODEL 512
#define HEADS  8
#define DHEAD  64
#define SPAN   64
#define STRIDE 4

#define MQ (B_SZ * LQ)    // 8192
#define MK (B_SZ * LKV)   // 2048

// ---------------- scratch (all single fp16 intermediates) ----------------
__device__ __half g_Qp [MQ * DMODEL];
__device__ __half g_Kp [MK * DMODEL];
__device__ __half g_Vp [MK * DMODEL];
__device__ __half g_ctx[MQ * DMODEL];
__device__ __half g_Wt [4 * DMODEL * DMODEL];    // transposed single-fp16 weights

// ---------------- helpers ----------------
__device__ __forceinline__ uint32_t smem_u32(const void* p) {
    uint32_t a;
    asm("{ .reg .u64 t; cvta.to.shared.u64 t, %1; cvt.u32.u64 %0, t; }" : "=r"(a) : "l"(p));
    return a;
}
__device__ __forceinline__ uint32_t pack_h2(float a, float b) {
    __half2 t(__float2half_rn(a), __float2half_rn(b));
    return *(uint32_t*)&t;
}
__device__ __forceinline__ void ldsm_x4(uint32_t* r, uint32_t a) {
    asm volatile("ldmatrix.sync.aligned.m8n8.x4.shared.b16 {%0,%1,%2,%3}, [%4];"
        : "=r"(r[0]), "=r"(r[1]), "=r"(r[2]), "=r"(r[3]) : "r"(a));
}
__device__ __forceinline__ void ldsm_x2(uint32_t* r, uint32_t a) {
    asm volatile("ldmatrix.sync.aligned.m8n8.x2.shared.b16 {%0,%1}, [%2];"
        : "=r"(r[0]), "=r"(r[1]) : "r"(a));
}
__device__ __forceinline__ void ldsm_x2_trans(uint32_t* r, uint32_t a) {
    asm volatile("ldmatrix.sync.aligned.m8n8.x2.trans.shared.b16 {%0,%1}, [%2];"
        : "=r"(r[0]), "=r"(r[1]) : "r"(a));
}
__device__ __forceinline__ void mma_f16(float* c, const uint32_t* a, const uint32_t* b) {
    asm volatile(
        "mma.sync.aligned.m16n8k16.row.col.f32.f16.f16.f32 "
        "{%0,%1,%2,%3}, {%4,%5,%6,%7}, {%8,%9}, {%0,%1,%2,%3};"
        : "+f"(c[0]), "+f"(c[1]), "+f"(c[2]), "+f"(c[3])
        : "r"(a[0]), "r"(a[1]), "r"(a[2]), "r"(a[3]), "r"(b[0]), "r"(b[1]));
}
__device__ __forceinline__ void cp16(uint32_t dst, const void* src) {
    asm volatile("cp.async.cg.shared.global [%0], [%1], 16;" :: "r"(dst), "l"(src));
}
#define CP_COMMIT() asm volatile("cp.async.commit_group;" ::: "memory")
#define CP_WAIT0()  asm volatile("cp.async.wait_group 0;" ::: "memory")
#define CP_WAIT1()  asm volatile("cp.async.wait_group 1;" ::: "memory")

// ---------------- prepass: transpose weights to single fp16 ----------------
__global__ __launch_bounds__(1024) void split_w_kernel(
    const float* __restrict__ W0, const float* __restrict__ W1,
    const float* __restrict__ W2, const float* __restrict__ W3,
    __half* __restrict__ Wt)
{
    __shared__ float t[32][33];
    const int z = blockIdx.z;
    const float* W = (z == 0) ? W0 : (z == 1) ? W1 : (z == 2) ? W2 : W3;
    const int n0 = blockIdx.x * 32, k0 = blockIdx.y * 32;
    const int tx = threadIdx.x, ty = threadIdx.y;
    t[ty][tx] = W[(size_t)(k0 + ty) * DMODEL + n0 + tx];
    __syncthreads();
    size_t o = (size_t)z * DMODEL * DMODEL + (size_t)(n0 + ty) * DMODEL + k0 + tx;
    Wt[o] = __float2half_rn(t[tx][ty]);
}

// ---------------- 3-stage cp.async fp16 GEMM ----------------
// C[128,128] = A[128,512] @ Bt[128,512]^T.
// AFP32: A fp32 in gmem, exact hi/lo split in-register (2-term). Stage = Ah|Al|B.
// !AFP32: A single fp16 (1-term). Stage = A|B.
#define GROWB 80
#define GTSZ  (128 * GROWB)        // 10240
#define NSTG  3
#define NCH   16                   // 512 / 32
#define SMEM_A3 (NSTG * 3 * GTSZ)  // 92160 (proj)
#define SMEM_A2 (NSTG * 2 * GTSZ)  // 61440 (outproj)

template<bool AFP32, bool OUT32>
__device__ __forceinline__ void gemm_pipe_tile(
    const float* __restrict__ A32, const __half* __restrict__ A16,
    const __half* __restrict__ B,
    float* __restrict__ Cf, __half* __restrict__ Ch,
    int row0, int col0)
{
    extern __shared__ char sm[];
    const uint32_t sb = smem_u32(sm);
    constexpr uint32_t NT  = AFP32 ? 3 : 2;       // tiles per stage
    constexpr uint32_t STG = NT * GTSZ;
    constexpr uint32_t BOFF = (NT - 1) * GTSZ;    // B tile offset within stage
    const int tid  = threadIdx.x;
    const int wid  = tid >> 5;
    const int lane = tid & 31;
    const int m0 = (wid & 1) * 64;
    const int n0 = (wid >> 1) * 32;

    float acc[4][4][4];
    #pragma unroll
    for (int mi = 0; mi < 4; mi++)
        #pragma unroll
        for (int ni = 0; ni < 4; ni++)
            #pragma unroll
            for (int e = 0; e < 4; e++) acc[mi][ni][e] = 0.0f;

    const uint32_t a_off = (uint32_t)(m0 + (lane & 15)) * GROWB + ((lane >> 4) << 4);
    const uint32_t b_off = (uint32_t)((lane & 7) + ((lane >> 4) & 1) * 8) * GROWB
                         + (((lane >> 3) & 1) << 4);

    const int ir0 = (tid + 0)   >> 2, ic0 = ((tid + 0)   & 3) << 4;
    const int ir1 = (tid + 256) >> 2, ic1 = ((tid + 256) & 3) << 4;

    float ar[2][8];

    auto ldA_regs = [&](int ch) {
        if (!AFP32) return;
        const int kc = ch * 32;
        {
            const float* pa = A32 + (size_t)(row0 + ir0) * DMODEL + kc + (ic0 >> 1);
            float4 x = *(const float4*)pa, y = *(const float4*)(pa + 4);
            ar[0][0]=x.x; ar[0][1]=x.y; ar[0][2]=x.z; ar[0][3]=x.w;
            ar[0][4]=y.x; ar[0][5]=y.y; ar[0][6]=y.z; ar[0][7]=y.w;
        }
        {
            const float* pa = A32 + (size_t)(row0 + ir1) * DMODEL + kc + (ic1 >> 1);
            float4 x = *(const float4*)pa, y = *(const float4*)(pa + 4);
            ar[1][0]=x.x; ar[1][1]=x.y; ar[1][2]=x.z; ar[1][3]=x.w;
            ar[1][4]=y.x; ar[1][5]=y.y; ar[1][6]=y.z; ar[1][7]=y.w;
        }
    };
    auto stsA = [&](int buf) {
        if (!AFP32) return;
        #pragma unroll
        for (int p = 0; p < 2; p++) {
            const int ir = p ? ir1 : ir0;
            const int ic = p ? ic1 : ic0;
            const float* a = ar[p];
            uint4 hi, lo;
            hi.x = pack_h2(a[0], a[1]); hi.y = pack_h2(a[2], a[3]);
            hi.z = pack_h2(a[4], a[5]); hi.w = pack_h2(a[6], a[7]);
            float l0 = a[0] - __half2float(__float2half_rn(a[0]));
            float l1 = a[1] - __half2float(__float2half_rn(a[1]));
            float l2 = a[2] - __half2float(__float2half_rn(a[2]));
            float l3 = a[3] - __half2float(__float2half_rn(a[3]));
            float l4 = a[4] - __half2float(__float2half_rn(a[4]));
            float l5 = a[5] - __half2float(__float2half_rn(a[5]));
            float l6 = a[6] - __half2float(__float2half_rn(a[6]));
            float l7 = a[7] - __half2float(__float2half_rn(a[7]));
            lo.x = pack_h2(l0, l1); lo.y = pack_h2(l2, l3);
            lo.z = pack_h2(l4, l5); lo.w = pack_h2(l6, l7);
            const uint32_t dso = (uint32_t)ir * GROWB + ic + (uint32_t)buf * STG;
            *(uint4*)(sm + 0 * GTSZ + dso) = hi;
            *(uint4*)(sm + 1 * GTSZ + dso) = lo;
        }
    };
    auto issue_cp = [&](int ch, int buf) {
        const uint32_t stg = sb + (uint32_t)buf * STG;
        const size_t kb = (size_t)ch * 64;
        #pragma unroll
        for (int p = 0; p < 2; p++) {
            const int ir = p ? ir1 : ir0;
            const int ic = p ? ic1 : ic0;
            const uint32_t dso = (uint32_t)ir * GROWB + ic;
            const size_t gb = (size_t)(col0 + ir) * (DMODEL * 2) + kb + ic;
            cp16(stg + BOFF + dso, (const char*)B + gb);
            if (!AFP32) {
                const size_t ga = (size_t)(row0 + ir) * (DMODEL * 2) + kb + ic;
                cp16(stg + 0 * GTSZ + dso, (const char*)A16 + ga);
            }
        }
        CP_COMMIT();
    };

    ldA_regs(0);
    issue_cp(0, 0);
    issue_cp(1, 1);

    for (int ch = 0; ch < NCH; ch++) {
        if (ch + 1 < NCH) CP_WAIT1(); else CP_WAIT0();
        __syncthreads();
        stsA(ch % NSTG);
        if (AFP32 && ch + 1 < NCH) ldA_regs(ch + 1);
        if (ch + 2 < NCH) issue_cp(ch + 2, (ch + 2) % NSTG);
        if (AFP32) __syncthreads();

        const uint32_t stg = sb + (uint32_t)(ch % NSTG) * STG;
        const uint32_t aH = stg + 0 * GTSZ + a_off;
        const uint32_t bB = stg + BOFF + b_off + (uint32_t)n0 * GROWB;

        #pragma unroll
        for (int ks = 0; ks < 2; ks++) {
            const uint32_t ko = (uint32_t)ks * 32;
            uint32_t bf[2][4], af[4][4];
            ldsm_x4(bf[0], bB + ko);
            ldsm_x4(bf[1], bB + (uint32_t)(16 * GROWB) + ko);
            #pragma unroll
            for (int mi = 0; mi < 4; mi++)
                ldsm_x4(af[mi], aH + (uint32_t)(mi * 16) * GROWB + ko);
            #pragma unroll
            for (int nj = 0; nj < 2; nj++)
                #pragma unroll
                for (int mi = 0; mi < 4; mi++) {
                    mma_f16(acc[mi][2 * nj + 0], af[mi], bf[nj] + 0);
                    mma_f16(acc[mi][2 * nj + 1], af[mi], bf[nj] + 2);
                }
            if (AFP32) {
                const uint32_t aL = stg + 1 * GTSZ + a_off;
                #pragma unroll
                for (int mi = 0; mi < 4; mi++)
                    ldsm_x4(af[mi], aL + (uint32_t)(mi * 16) * GROWB + ko);
                #pragma unroll
                for (int nj = 0; nj < 2; nj++)
                    #pragma unroll
                    for (int mi = 0; mi < 4; mi++) {
                        mma_f16(acc[mi][2 * nj + 0], af[mi], bf[nj] + 0);
                        mma_f16(acc[mi][2 * nj + 1], af[mi], bf[nj] + 2);
                    }
            }
        }
        if (!AFP32) __syncthreads();     // buffer stable until all warps done
    }

    #pragma unroll
    for (int mi = 0; mi < 4; mi++) {
        #pragma unroll
        for (int ni = 0; ni < 4; ni++) {
            const int row = row0 + m0 + mi * 16 + (lane >> 2);
            const int col = col0 + n0 + ni * 8 + (lane & 3) * 2;
            const float* a = acc[mi][ni];
            if (OUT32) {
                *(float2*)&Cf[(size_t)row * DMODEL + col] = make_float2(a[0], a[1]);
                *(float2*)&Cf[(size_t)(row + 8) * DMODEL + col] = make_float2(a[2], a[3]);
            } else {
                *(__half2*)&Ch[(size_t)row * DMODEL + col] =
                    __half2(__float2half_rn(a[0]), __float2half_rn(a[1]));
                *(__half2*)&Ch[(size_t)(row + 8) * DMODEL + col] =
                    __half2(__float2half_rn(a[2]), __float2half_rn(a[3]));
            }
        }
    }
}

__global__ __launch_bounds__(256, 2) void proj_fused_kernel(
    const float* __restrict__ q, const float* __restrict__ k, const float* __restrict__ v,
    const __half* __restrict__ Wt,
    __half* __restrict__ Qp, __half* __restrict__ Kp, __half* __restrict__ Vp)
{
    const int bid = blockIdx.x;
    const size_t WSZ = (size_t)DMODEL * DMODEL;
    const float* A; const __half* B; __half* C; int t;
    if (bid < 256)      { A = q; B = Wt;           C = Qp; t = bid; }
    else if (bid < 320) { A = k; B = Wt + WSZ;     C = Kp; t = bid - 256; }
    else                { A = v; B = Wt + 2 * WSZ; C = Vp; t = bid - 320; }
    gemm_pipe_tile<true, false>(A, nullptr, B, nullptr, C,
                                (t >> 2) * 128, (t & 3) * 128);
}

__global__ __launch_bounds__(256, 2) void outproj_kernel(
    const __half* __restrict__ ctx, const __half* __restrict__ Wt,
    float* __restrict__ out)
{
    const size_t WSZ = (size_t)DMODEL * DMODEL;
    gemm_pipe_tile<false, true>(nullptr, ctx, Wt + 3 * WSZ, out, nullptr,
                                blockIdx.y * 128, blockIdx.x * 128);
}

// ---------------- tensor-core sparse attention (all single fp16) ----------------
#define AROWB 144
#define SQ 0
#define SK (64 * AROWB)             // 9216
#define SV (96 * AROWB)             // 13824
#define ATT_SM (128 * AROWB)        // 18432

__global__ __launch_bounds__(128) void attn_tc_kernel(
    const __half* __restrict__ Qp, const __half* __restrict__ Kp,
    const __half* __restrict__ Vp, __half* __restrict__ ctx)
{
    __shared__ char sm[ATT_SM];
    const uint32_t sb = smem_u32(sm);
    const int c0  = blockIdx.x * 64;
    const int h   = blockIdx.y;
    const int b   = blockIdx.z;
    const int tid = threadIdx.x;
    const int wid = tid >> 5;
    const int lane = tid & 31;

    int jmin = (c0 - (SPAN - 1) + (STRIDE - 1)) >> 2;
    if (jmin < 0) jmin = 0;
    int jmax = (c0 + 63) >> 2;
    if (jmax > LKV - 1) jmax = LKV - 1;
    const int nrows = jmax - jmin + 1;                  // <= 32

    // zero V tail rows (weight-0 rows must not be NaN)
    for (int u = tid; u < (32 - nrows) * 36; u += 128) {
        const int r = nrows + u / 36, w = u % 36;
        ((uint32_t*)(sm + SV))[r * 36 + w] = 0;
    }
    // Q tile (64 rows x 128B)
    for (int u = tid; u < 512; u += 128) {
        const int r = u >> 3, cb = (u & 7) << 4;
        const size_t gb = (size_t)(b * LQ + c0 + r) * (DMODEL * 2) + h * DHEAD * 2 + cb;
        *(uint4*)(sm + SQ + r * AROWB + cb) = *(const uint4*)((const char*)Qp + gb);
    }
    // K + V window rows
    for (int u = tid; u < nrows * 8; u += 128) {
        const int r = u >> 3, cb = (u & 7) << 4;
        const size_t gb = (size_t)(b * LKV + jmin + r) * (DMODEL * 2) + h * DHEAD * 2 + cb;
        *(uint4*)(sm + SK + r * AROWB + cb) = *(const uint4*)((const char*)Kp + gb);
        *(uint4*)(sm + SV + r * AROWB + cb) = *(const uint4*)((const char*)Vp + gb);
    }
    __syncthreads();

    // ---- S = Q @ K^T (single term) ----
    float s[4][4];
    #pragma unroll
    for (int ni = 0; ni < 4; ni++)
        #pragma unroll
        for (int e = 0; e < 4; e++) s[ni][e] = 0.0f;

    const uint32_t qa = sb + SQ + (uint32_t)(wid * 16 + (lane & 15)) * AROWB + ((lane >> 4) << 4);
    const uint32_t kb = sb + SK + (uint32_t)(lane & 7) * AROWB + (((lane >> 3) & 1) << 4);
    #pragma unroll
    for (int ks = 0; ks < 4; ks++) {
        const uint32_t ko = (uint32_t)ks * 32;
        uint32_t q4[4], b2[2];
        ldsm_x4(q4, qa + ko);
        #pragma unroll
        for (int ni = 0; ni < 4; ni++) {
            ldsm_x2(b2, kb + (uint32_t)(ni * 8) * AROWB + ko);
            mma_f16(s[ni], q4, b2);
        }
    }

    // ---- mask + scale ----
    const int r_lo = c0 + wid * 16 + (lane >> 2);
    const int r_hi = r_lo + 8;
    #pragma unroll
    for (int ni = 0; ni < 4; ni++) {
        #pragma unroll
        for (int e = 0; e < 4; e++) {
            const int col_abs = jmin + ni * 8 + (lane & 3) * 2 + (e & 1);
            const int c = (e < 2) ? r_lo : r_hi;
            const bool valid = (unsigned)(c - 4 * col_abs) < (unsigned)SPAN;
            s[ni][e] = valid ? s[ni][e] * 0.125f : -1e30f;
        }
    }

    // ---- softmax over quad ----
    float mx0 = -1e30f, mx1 = -1e30f;
    #pragma unroll
    for (int ni = 0; ni < 4; ni++) {
        mx0 = fmaxf(mx0, fmaxf(s[ni][0], s[ni][1]));
        mx1 = fmaxf(mx1, fmaxf(s[ni][2], s[ni][3]));
    }
    mx0 = fmaxf(mx0, __shfl_xor_sync(0xffffffffu, mx0, 1));
    mx0 = fmaxf(mx0, __shfl_xor_sync(0xffffffffu, mx0, 2));
    mx1 = fmaxf(mx1, __shfl_xor_sync(0xffffffffu, mx1, 1));
    mx1 = fmaxf(mx1, __shfl_xor_sync(0xffffffffu, mx1, 2));
    float sum0 = 0.0f, sum1 = 0.0f;
    #pragma unroll
    for (int ni = 0; ni < 4; ni++) {
        s[ni][0] = __expf(s[ni][0] - mx0); sum0 += s[ni][0];
        s[ni][1] = __expf(s[ni][1] - mx0); sum0 += s[ni][1];
        s[ni][2] = __expf(s[ni][2] - mx1); sum1 += s[ni][2];
        s[ni][3] = __expf(s[ni][3] - mx1); sum1 += s[ni][3];
    }
    sum0 += __shfl_xor_sync(0xffffffffu, sum0, 1);
    sum0 += __shfl_xor_sync(0xffffffffu, sum0, 2);
    sum1 += __shfl_xor_sync(0xffffffffu, sum1, 1);
    sum1 += __shfl_xor_sync(0xffffffffu, sum1, 2);
    const float inv0 = 1.0f / sum0, inv1 = 1.0f / sum1;
    #pragma unroll
    for (int ni = 0; ni < 4; ni++) {
        s[ni][0] *= inv0; s[ni][1] *= inv0;
        s[ni][2] *= inv1; s[ni][3] *= inv1;
    }

    // ---- pack P frags (single) ----
    uint32_t aP[2][4];
    #pragma unroll
    for (int kc = 0; kc < 2; kc++) {
        #pragma unroll
        for (int half = 0; half < 2; half++) {
            const float* p = s[2 * kc + half];
            aP[kc][half * 2 + 0] = pack_h2(p[0], p[1]);
            aP[kc][half * 2 + 1] = pack_h2(p[2], p[3]);
        }
    }

    // ---- O = P @ V (single term, ldmatrix.trans) ----
    float o[8][4];
    #pragma unroll
    for (int ni = 0; ni < 8; ni++)
        #pragma unroll
        for (int e = 0; e < 4; e++) o[ni][e] = 0.0f;
    const uint32_t vrow = (uint32_t)((lane & 7) + ((lane >> 3) & 1) * 8) * AROWB;
    #pragma unroll
    for (int kc = 0; kc < 2; kc++) {
        const uint32_t kro = (uint32_t)(kc * 16) * AROWB;
        #pragma unroll
        for (int ni = 0; ni < 8; ni++) {
            uint32_t b2[2];
            ldsm_x2_trans(b2, sb + SV + kro + vrow + (uint32_t)(ni * 16));
            mma_f16(o[ni], aP[kc], b2);
        }
    }

    // ---- store ctx (single fp16) ----
    #pragma unroll
    for (int ni = 0; ni < 8; ni++) {
        const int col = ni * 8 + (lane & 3) * 2;
        const size_t i0 = (size_t)(b * LQ + r_lo) * DMODEL + h * DHEAD + col;
        const size_t i1 = (size_t)(b * LQ + r_hi) * DMODEL + h * DHEAD + col;
        *(__half2*)&ctx[i0] =
            __half2(__float2half_rn(o[ni][0]), __float2half_rn(o[ni][1]));
        *(__half2*)&ctx[i1] =
            __half2(__float2half_rn(o[ni][2]), __float2half_rn(o[ni][3]));
    }
}

// ---------------- launch ----------------
extern "C" void kernel_launch(void* const* d_in, const int* in_sizes, int n_in,
                              void* d_out, int out_size)
{
    const float* q    = (const float*)d_in[0];
    const float* k    = (const float*)d_in[1];
    const float* v    = (const float*)d_in[2];
    const float* Wq   = (const float*)d_in[3];
    const float* Wk   = (const float*)d_in[4];
    const float* Wv   = (const float*)d_in[5];
    const float* Wout = (const float*)d_in[6];
    float* out = (float*)d_out;

    __half *Qp, *Kp, *Vp, *ctx, *Wt;
    cudaGetSymbolAddress((void**)&Qp,  g_Qp);
    cudaGetSymbolAddress((void**)&Kp,  g_Kp);
    cudaGetSymbolAddress((void**)&Vp,  g_Vp);
    cudaGetSymbolAddress((void**)&ctx, g_ctx);
    cudaGetSymbolAddress((void**)&Wt,  g_Wt);

    cudaFuncSetAttribute(proj_fused_kernel,
                         cudaFuncAttributeMaxDynamicSharedMemorySize, SMEM_A3);
    cudaFuncSetAttribute(outproj_kernel,
                         cudaFuncAttributeMaxDynamicSharedMemorySize, SMEM_A2);

    split_w_kernel<<<dim3(16, 16, 4), dim3(32, 32)>>>(Wq, Wk, Wv, Wout, Wt);
    proj_fused_kernel<<<384, 256, SMEM_A3>>>(q, k, v, Wt, Qp, Kp, Vp);
    attn_tc_kernel<<<dim3(LQ / 64, HEADS, B_SZ), 128>>>(Qp, Kp, Vp, ctx);
    outproj_kernel<<<dim3(4, 64), 256, SMEM_A2>>>(ctx, Wt, out);
}